// round 10
// baseline (speedup 1.0000x reference)
#include <cuda_runtime.h>
#include <cstdint>

#define DD 256
#define NTOK 16384
#define KCB 8192
#define BM 128
#define BN 256
#define NMB (NTOK/BM)     // 128
#define NNT (KCB/BN)      // 32
#define UNITS (NMB*NNT)   // 4096
#define GRID1 148
#define STGB 49152        // 16KB A + 32KB B
#define BARS (4*STGB)
#define RED  (BARS+128)
#define SMEMSZ (RED + 24576)
#define NTHR 512
#define FLAG_T 0.12f
#define FLAG_CAP 4096
#define P2M 64

// A packed: [mb][dc] -> 16KB contiguous ([tl 8][ks 4][lane 32] float4)
__device__ __align__(128) float4 g_xp[NTOK*DD/4];
// B packed: [nt][dc] -> 32KB contiguous ([pair 16][ks 4][lane 32] float4-as-2xfloat2)
__device__ __align__(128) float2 g_ep[KCB*DD/2];
__device__ __align__(128) float g_esq[KCB];
// per-(nt,row) slot planes
__device__ float g_m1p[NNT*NTOK];
__device__ float g_m2p[NNT*NTOK];
__device__ int   g_i1p[NNT*NTOK];
__device__ unsigned long long g_best[NTOK];
__device__ int g_flag[FLAG_CAP];
__device__ int g_cnt;

__device__ __forceinline__ uint32_t s2u(const void* p){
    uint32_t a; asm("{ .reg .u64 t; cvta.to.shared.u64 t, %1; cvt.u32.u64 %0, t; }":"=r"(a):"l"(p)); return a;
}
#define MBAR_INIT(a,c) asm volatile("mbarrier.init.shared.b64 [%0], %1;"::"r"(a),"r"(c):"memory")
#define MBAR_ARRIVE(a) asm volatile("mbarrier.arrive.shared.b64 _, [%0];"::"r"(a):"memory")
#define MBAR_EXPECT_TX(a,tx) asm volatile("mbarrier.arrive.expect_tx.shared.b64 _, [%0], %1;"::"r"(a),"r"(tx):"memory")
#define MBAR_WAIT(a,p) do{ uint32_t _m=(a),_p=(p),_d; \
    asm volatile("{\n\t.reg .pred q;\n\tmbarrier.try_wait.parity.acquire.cta.shared::cta.b64 q,[%1],%2;\n\tselp.b32 %0,1,0,q;\n\t}":"=r"(_d):"r"(_m),"r"(_p):"memory"); \
    if(!_d){ asm volatile("{\n\t.reg .pred q;\n\tW%=:\n\tmbarrier.try_wait.parity.acquire.cta.shared::cta.b64 q,[%0],%1,0x989680;\n\t@q bra.uni DN%=;\n\tbra.uni W%=;\n\tDN%=:\n\t}"::"r"(_m),"r"(_p):"memory"); } }while(0)
#define BULK_G2S(d,s,n,mb) asm volatile( \
    "cp.async.bulk.shared::cluster.global.mbarrier::complete_tx::bytes [%0], [%1], %2, [%3];" \
    :: "r"((uint32_t)(d)),"l"(s),"r"((uint32_t)(n)),"r"((uint32_t)(mb)) : "memory")

__device__ __forceinline__ void mma8(float* d, const uint32_t* a, const uint32_t* b){
    asm("mma.sync.aligned.m16n8k8.row.col.f32.tf32.tf32.f32 "
        "{%0,%1,%2,%3}, {%4,%5,%6,%7}, {%8,%9}, {%0,%1,%2,%3};"
        : "+f"(d[0]),"+f"(d[1]),"+f"(d[2]),"+f"(d[3])
        : "r"(a[0]),"r"(a[1]),"r"(a[2]),"r"(a[3]),"r"(b[0]),"r"(b[1]));
}
__device__ __forceinline__ float tf32r(float x){
    uint32_t b; asm("cvt.rna.tf32.f32 %0, %1;":"=r"(b):"f"(x)); return __uint_as_float(b);
}

// ---- prep: pack A ([mb][dc] 16KB blocks) ----
__global__ void packA(const float* __restrict__ src, float4* __restrict__ dst){
    int i = blockIdx.x*blockDim.x + threadIdx.x;
    int lane = i&31, ks = (i>>5)&3, tl = (i>>7)&7, dc = (i>>10)&7, mb = i>>13;
    int gr = lane>>2, gc = lane&3;
    int r0 = (mb*8+tl)*16 + gr, c0 = (dc*4+ks)*8 + gc;
    float4 v;
    v.x = tf32r(src[(size_t)r0*DD + c0]);
    v.y = tf32r(src[(size_t)(r0+8)*DD + c0]);
    v.z = tf32r(src[(size_t)r0*DD + c0+4]);
    v.w = tf32r(src[(size_t)(r0+8)*DD + c0+4]);
    dst[i] = v;
}
// ---- prep: pack B ([nt][dc] 32KB blocks, n8-tiles paired for LDS.128) ----
__global__ void packB(const float* __restrict__ src, float2* __restrict__ dst){
    int i = blockIdx.x*blockDim.x + threadIdx.x;
    int lane = i&31, ks = (i>>5)&3, ntl = (i>>7)&31, dc = (i>>12)&7, nt = i>>15;
    int gr = lane>>2, gc = lane&3;
    int r = (nt*32+ntl)*8 + gr, c0 = (dc*4+ks)*8 + gc;
    float2 v;
    v.x = tf32r(src[(size_t)r*DD + c0]);
    v.y = tf32r(src[(size_t)r*DD + c0+4]);
    // paired layout: byte off within (nt,dc) block = (((ntl>>1)*4+ks)*32+lane)*16 + (ntl&1)*8
    size_t blk = (size_t)(nt*8+dc)*32768;
    size_t off = blk + ((((size_t)(ntl>>1)*4+ks)*32+lane)<<4) + ((ntl&1)<<3);
    dst[off>>3] = v;
}
__global__ void sumsq_kernel(const float* __restrict__ x, float* __restrict__ o, int rows){
    if(blockIdx.x==0 && threadIdx.x==0) g_cnt = 0;
    int row = blockIdx.x*(blockDim.x>>5) + (threadIdx.x>>5); if(row>=rows) return;
    int lane = threadIdx.x&31; const float* p = x + (size_t)row*DD; float s=0.f;
    #pragma unroll
    for(int c=lane;c<DD;c+=32){ float v=p[c]; s+=v*v; }
    #pragma unroll
    for(int ofs=16;ofs;ofs>>=1) s+=__shfl_down_sync(0xffffffffu,s,ofs);
    if(!lane) o[row]=s;
}

__device__ __forceinline__ void prefetch_it(uint32_t sb, uint32_t fullb, int j, int cta){
    const int ui = j>>3, dc = j&7;
    const int u = cta + GRID1*ui;
    const int mb = u & (NMB-1), nt = u >> 7;
    const int sj = j&3;
    MBAR_EXPECT_TX(fullb+sj*8, STGB);
    const char* srcA = (const char*)g_xp + ((size_t)(mb*8+dc))*16384;
    const char* srcB = (const char*)g_ep + ((size_t)(nt*8+dc))*32768;
    BULK_G2S(sb + sj*STGB,         srcA, 16384, fullb+sj*8);
    BULK_G2S(sb + sj*STGB + 16384, srcB, 32768, fullb+sj*8);
}

// ---- phase 1: persistent tf32 GEMM, per-unit slot output ----
__global__ void __launch_bounds__(NTHR,1) vq_phase1(const float* __restrict__ esq)
{
    extern __shared__ char smem[];
    const uint32_t sb = s2u(smem);
    const int tid = threadIdx.x, wid = tid>>5, lane = tid&31;
    const int r = lane>>2, c = lane&3;
    const int wm = wid&3, wn = wid>>2;     // 4x4 warp grid, warp tile 32x64
    const int cta = blockIdx.x;
    const int nu = (UNITS - cta + GRID1 - 1)/GRID1;
    const int NITL = nu*8;

    const uint32_t fullb  = sb + BARS;
    const uint32_t emptyb = sb + BARS + 32;
    float* s_m1 = (float*)(smem + RED);
    float* s_m2 = (float*)(smem + RED + 8192);
    int*   s_i1 = (int*)(smem + RED + 16384);

    if(tid==0){
        #pragma unroll
        for(int s=0;s<4;s++){ MBAR_INIT(fullb+s*8,1); MBAR_INIT(emptyb+s*8,16); }
    }
    __syncthreads();
    if(tid==0){
        #pragma unroll
        for(int j=0;j<3;j++) prefetch_it(sb, fullb, j, cta);
    }

    for(int ui=0; ui<nu; ui++){
        const int u = cta + GRID1*ui;
        const int mb_u = u & (NMB-1), nt_u = u >> 7;

        float m1[4], m2[4]; int i1[4];
        #pragma unroll
        for(int i=0;i<4;i++){ m1[i]=3.4e38f; m2[i]=3.4e38f; i1[i]=0; }
        float acc[2][8][4];
        #pragma unroll
        for(int m=0;m<2;m++)
            #pragma unroll
            for(int n=0;n<8;n++){ acc[m][n][0]=0.f;acc[m][n][1]=0.f;acc[m][n][2]=0.f;acc[m][n][3]=0.f; }

        for(int dc=0; dc<8; dc++){
            const int j = ui*8 + dc;
            const int s = j&3;
            MBAR_WAIT(fullb+s*8, (j>>2)&1);
            const char* stp = smem + (size_t)s*STGB;

            #pragma unroll
            for(int ks=0; ks<4; ks++){
                float4 af[2]; float4 bq[4];
                #pragma unroll
                for(int m=0;m<2;m++)
                    af[m] = *(const float4*)(stp + ((wm*2+m)*4+ks)*512 + lane*16);
                #pragma unroll
                for(int p=0;p<4;p++)
                    bq[p] = *(const float4*)(stp + 16384 + ((wn*4+p)*4+ks)*512 + lane*16);
                #pragma unroll
                for(int m=0;m<2;m++)
                    #pragma unroll
                    for(int p=0;p<4;p++){
                        mma8(acc[m][2*p],   (const uint32_t*)&af[m], (const uint32_t*)&bq[p].x);
                        mma8(acc[m][2*p+1], (const uint32_t*)&af[m], (const uint32_t*)&bq[p].z);
                    }
            }
            __syncwarp();
            if(lane==0) MBAR_ARRIVE(emptyb+s*8);
            if(tid==0 && j+3 < NITL){
                const int jj = j+3, sj = jj&3;
                if(jj>=4) MBAR_WAIT(emptyb+sj*8, ((jj>>2)-1)&1);
                prefetch_it(sb, fullb, jj, cta);
            }
        }
        // fold this unit's 256 cols
        #pragma unroll
        for(int m=0;m<2;m++){
            const int rl=2*m, rh=2*m+1;
            #pragma unroll
            for(int n=0;n<8;n++){
                int colb = nt_u*BN + wn*64 + n*8 + 2*c;
                float e0 = __ldg(esq+colb), e1 = __ldg(esq+colb+1);
                float d;
                d = e0 - 2.f*acc[m][n][0];
                if(d<m1[rl]){m2[rl]=m1[rl];m1[rl]=d;i1[rl]=colb;} else if(d<m2[rl]) m2[rl]=d;
                d = e1 - 2.f*acc[m][n][1];
                if(d<m1[rl]){m2[rl]=m1[rl];m1[rl]=d;i1[rl]=colb+1;} else if(d<m2[rl]) m2[rl]=d;
                d = e0 - 2.f*acc[m][n][2];
                if(d<m1[rh]){m2[rh]=m1[rh];m1[rh]=d;i1[rh]=colb;} else if(d<m2[rh]) m2[rh]=d;
                d = e1 - 2.f*acc[m][n][3];
                if(d<m1[rh]){m2[rh]=m1[rh];m1[rh]=d;i1[rh]=colb+1;} else if(d<m2[rh]) m2[rh]=d;
            }
        }
        // per-unit cross-thread reduce (16 candidates per row)
        __syncthreads();
        #pragma unroll
        for(int i=0;i<4;i++){
            int row  = wm*32 + (i>>1)*16 + r + (i&1)*8;
            int slot = wn*4 + c;
            s_m1[row*16+slot] = m1[i];
            s_m2[row*16+slot] = m2[i];
            s_i1[row*16+slot] = i1[i];
        }
        __syncthreads();
        if(tid < 128){
            float bd = 3.4e38f; int bi = 0, tw = 0;
            #pragma unroll
            for(int t=0;t<16;t++){
                float d = s_m1[tid*16+t]; int ii = s_i1[tid*16+t];
                if(d<bd || (d==bd && ii<bi)){ bd=d; bi=ii; tw=t; }
            }
            float b2 = 3.4e38f;
            #pragma unroll
            for(int t=0;t<16;t++){
                float v = (t==tw) ? s_m2[tid*16+t] : s_m1[tid*16+t];
                b2 = fminf(b2, v);
            }
            int gro = nt_u*NTOK + mb_u*BM + tid;
            g_m1p[gro] = bd; g_m2p[gro] = b2; g_i1p[gro] = bi;
        }
        __syncthreads();
    }
}

// ---- merge: global min1/min2 across nt slots, flag, outi + gather ----
__global__ void __launch_bounds__(128) vq_merge(
    const float* __restrict__ E, float* __restrict__ outq, float* __restrict__ outi)
{
    __shared__ int s_idx[128];
    const int tid = threadIdx.x;
    const int row = blockIdx.x*128 + tid;
    float bd = 3.4e38f, b2 = 3.4e38f; int bi = 0;
    #pragma unroll 4
    for(int nt=0; nt<NNT; nt++){
        float d  = g_m1p[nt*NTOK + row];
        int   ii = g_i1p[nt*NTOK + row];
        float d2 = g_m2p[nt*NTOK + row];
        if(d<bd || (d==bd && ii<bi)){ b2 = fminf(bd, d2); bd = d; bi = ii; }
        else b2 = fminf(b2, d);
    }
    s_idx[tid] = bi;
    outi[row] = (float)bi;
    if(b2 - bd < FLAG_T){
        g_best[row] = 0xFFFFFFFFFFFFFFFFull;
        int pos = atomicAdd(&g_cnt, 1);
        if(pos < FLAG_CAP) g_flag[pos] = row;
    }
    __syncthreads();
    const int m0 = blockIdx.x*128;
    for(int f=tid; f<128*(DD/4); f+=128){
        int rr = f>>6, c4 = f&63;
        float4 v = *(const float4*)(E + (size_t)s_idx[rr]*DD + c4*4);
        *(float4*)(outq + (size_t)(m0+rr)*DD + c4*4) = v;
    }
}

// ---- phase 2: exact fp32 rescore, K-split, atomicMin merge ----
__global__ void __launch_bounds__(128) vq_phase2(
    const float* __restrict__ X, const float* __restrict__ E, const float* __restrict__ esq)
{
    int cnt = g_cnt; if(cnt > FLAG_CAP) cnt = FLAG_CAP;
    const int rb = blockIdx.x;
    if(rb*P2M >= cnt) return;
    const int k0 = blockIdx.y * 128;
    __shared__ float Xs[16][P2M];
    __shared__ float Es[16][128];
    __shared__ int rows[P2M];
    __shared__ float s_bd[16][P2M];
    __shared__ int   s_bi[16][P2M];
    const int tid = threadIdx.x;
    const int tx = tid&15, ty = tid>>4;
    if(tid < P2M){
        int fi = rb*P2M + tid; if(fi >= cnt) fi = cnt-1;
        rows[tid] = g_flag[fi];
    }
    __syncthreads();

    float acc[8][8];
    #pragma unroll
    for(int i=0;i<8;i++)
        #pragma unroll
        for(int j=0;j<8;j++) acc[i][j]=0.f;

    for(int d0=0; d0<DD; d0+=16){
        #pragma unroll
        for(int l=0;l<2;l++){
            int f = tid + l*128, rr = f>>2, c4 = f&3;
            float4 v = *(const float4*)(X + (size_t)rows[rr]*DD + d0 + c4*4);
            Xs[c4*4+0][rr]=v.x; Xs[c4*4+1][rr]=v.y; Xs[c4*4+2][rr]=v.z; Xs[c4*4+3][rr]=v.w;
        }
        #pragma unroll
        for(int l=0;l<4;l++){
            int f = tid + l*128, rr = f>>2, c4 = f&3;
            float4 v = *(const float4*)(E + (size_t)(k0+rr)*DD + d0 + c4*4);
            Es[c4*4+0][rr]=v.x; Es[c4*4+1][rr]=v.y; Es[c4*4+2][rr]=v.z; Es[c4*4+3][rr]=v.w;
        }
        __syncthreads();
        #pragma unroll
        for(int kk=0;kk<16;kk++){
            float xr[8], er[8];
            #pragma unroll
            for(int i=0;i<8;i++) xr[i]=Xs[kk][ty*8+i];
            #pragma unroll
            for(int j=0;j<8;j++) er[j]=Es[kk][tx*8+j];
            #pragma unroll
            for(int i=0;i<8;i++)
                #pragma unroll
                for(int j=0;j<8;j++) acc[i][j]=fmaf(xr[i],er[j],acc[i][j]);
        }
        __syncthreads();
    }
    float bd[8]; int bi[8];
    #pragma unroll
    for(int i=0;i<8;i++){ bd[i]=3.4e38f; bi[i]=0; }
    #pragma unroll
    for(int i=0;i<8;i++)
        #pragma unroll
        for(int j=0;j<8;j++){
            int col = k0 + tx*8 + j;
            float d = __ldg(esq+col) - 2.f*acc[i][j];
            if(d < bd[i]){ bd[i]=d; bi[i]=col; }
        }
    #pragma unroll
    for(int i=0;i<8;i++){ s_bd[tx][ty*8+i]=bd[i]; s_bi[tx][ty*8+i]=bi[i]; }
    __syncthreads();
    if(tid < P2M){
        float b = s_bd[0][tid]; int ii = s_bi[0][tid];
        #pragma unroll
        for(int t=1;t<16;t++){
            float d = s_bd[t][tid]; int jj = s_bi[t][tid];
            if(d<b || (d==b && jj<ii)){ b=d; ii=jj; }
        }
        if(rb*P2M + tid < cnt){
            uint32_t u = __float_as_uint(b);
            u = (u & 0x80000000u) ? ~u : (u | 0x80000000u);
            unsigned long long key = ((unsigned long long)u << 32) | (unsigned)ii;
            atomicMin(&g_best[rows[tid]], key);
        }
    }
}

// ---- phase 3: write back flagged rows ----
__global__ void __launch_bounds__(256) vq_phase3(
    const float* __restrict__ E, float* __restrict__ outq, float* __restrict__ outi)
{
    int cnt = g_cnt; if(cnt > FLAG_CAP) cnt = FLAG_CAP;
    int i = blockIdx.x*8 + (threadIdx.x>>5);
    if(i >= cnt) return;
    int lane = threadIdx.x&31;
    int row = g_flag[i];
    int bi = (int)(g_best[row] & 0xFFFFFFFFull);
    if(lane==0) outi[row] = (float)bi;
    float4 v0 = *(const float4*)(E + (size_t)bi*DD + lane*8);
    float4 v1 = *(const float4*)(E + (size_t)bi*DD + lane*8 + 4);
    *(float4*)(outq + (size_t)row*DD + lane*8)     = v0;
    *(float4*)(outq + (size_t)row*DD + lane*8 + 4) = v1;
}

extern "C" void kernel_launch(void* const* d_in, const int* in_sizes, int n_in,
                              void* d_out, int out_size) {
    const float* X = (const float*)d_in[0];
    const float* E = (const float*)d_in[1];

    float4* xp; float2* ep; float* esq;
    cudaGetSymbolAddress((void**)&xp, g_xp);
    cudaGetSymbolAddress((void**)&ep, g_ep);
    cudaGetSymbolAddress((void**)&esq, g_esq);

    packA<<<NTOK*DD/4/256, 256>>>(X, xp);
    packB<<<KCB*DD/2/256, 256>>>(E, ep);
    sumsq_kernel<<<KCB/8, 256>>>(E, esq, KCB);   // also zeroes g_cnt

    float* outq = (float*)d_out;
    float* outi = (float*)d_out + (size_t)NTOK*DD;

    cudaFuncSetAttribute(vq_phase1, cudaFuncAttributeMaxDynamicSharedMemorySize, SMEMSZ);
    vq_phase1<<<GRID1, NTHR, SMEMSZ>>>(esq);
    vq_merge<<<NTOK/128, 128>>>(E, outq, outi);
    vq_phase2<<<dim3(FLAG_CAP/P2M, KCB/128), 128>>>(X, E, esq);
    vq_phase3<<<FLAG_CAP/8, 256>>>(E, outq, outi);
}

// round 11
// speedup vs baseline: 1.1026x; 1.1026x over previous
#include <cuda_runtime.h>
#include <cstdint>

#define DD 256
#define NTOK 16384
#define KCB 8192
#define BM 128
#define BN 256
#define NMB (NTOK/BM)     // 128
#define NNT (KCB/BN)      // 32
#define NIT (NNT*8)       // 256
#define ASZ 131072        // full A panel (8 dc x 16KB)
#define BSTG 32768
#define NSTG 3
#define BOFF ASZ
#define BARS (ASZ + NSTG*BSTG)   // 229376
#define SMEMSZ (BARS + 256)
#define NTHR 512
#define FLAG_T 0.12f
#define FLAG_CAP 4096
#define P2M 64

// A packed: [mb][dc] -> 16KB contiguous ([tl 8][ks 4][lane 32] float4)
__device__ __align__(128) float4 g_xp[NTOK*DD/4];
// B packed: [nt][dc] -> 32KB contiguous, n8-tiles paired for LDS.128
__device__ __align__(128) float2 g_ep[KCB*DD/2];
__device__ __align__(128) float g_esq[KCB];
__device__ unsigned long long g_best[NTOK];
__device__ int g_flag[FLAG_CAP];
__device__ int g_cnt;

__device__ __forceinline__ uint32_t s2u(const void* p){
    uint32_t a; asm("{ .reg .u64 t; cvta.to.shared.u64 t, %1; cvt.u32.u64 %0, t; }":"=r"(a):"l"(p)); return a;
}
#define MBAR_INIT(a,c) asm volatile("mbarrier.init.shared.b64 [%0], %1;"::"r"(a),"r"(c):"memory")
#define MBAR_ARRIVE(a) asm volatile("mbarrier.arrive.shared.b64 _, [%0];"::"r"(a):"memory")
#define MBAR_EXPECT_TX(a,tx) asm volatile("mbarrier.arrive.expect_tx.shared.b64 _, [%0], %1;"::"r"(a),"r"(tx):"memory")
#define MBAR_WAIT(a,p) do{ uint32_t _m=(a),_p=(p),_d; \
    asm volatile("{\n\t.reg .pred q;\n\tmbarrier.try_wait.parity.acquire.cta.shared::cta.b64 q,[%1],%2;\n\tselp.b32 %0,1,0,q;\n\t}":"=r"(_d):"r"(_m),"r"(_p):"memory"); \
    if(!_d){ asm volatile("{\n\t.reg .pred q;\n\tW%=:\n\tmbarrier.try_wait.parity.acquire.cta.shared::cta.b64 q,[%0],%1,0x989680;\n\t@q bra.uni DN%=;\n\tbra.uni W%=;\n\tDN%=:\n\t}"::"r"(_m),"r"(_p):"memory"); } }while(0)
#define BULK_G2S(d,s,n,mb) asm volatile( \
    "cp.async.bulk.shared::cluster.global.mbarrier::complete_tx::bytes [%0], [%1], %2, [%3];" \
    :: "r"((uint32_t)(d)),"l"(s),"r"((uint32_t)(n)),"r"((uint32_t)(mb)) : "memory")

__device__ __forceinline__ void mma8(float* d, const uint32_t* a, const uint32_t* b){
    asm("mma.sync.aligned.m16n8k8.row.col.f32.tf32.tf32.f32 "
        "{%0,%1,%2,%3}, {%4,%5,%6,%7}, {%8,%9}, {%0,%1,%2,%3};"
        : "+f"(d[0]),"+f"(d[1]),"+f"(d[2]),"+f"(d[3])
        : "r"(a[0]),"r"(a[1]),"r"(a[2]),"r"(a[3]),"r"(b[0]),"r"(b[1]));
}
__device__ __forceinline__ float tf32r(float x){
    uint32_t b; asm("cvt.rna.tf32.f32 %0, %1;":"=r"(b):"f"(x)); return __uint_as_float(b);
}

// ---- prep: pack A ([mb][dc] 16KB blocks) ----
__global__ void packA(const float* __restrict__ src, float4* __restrict__ dst){
    int i = blockIdx.x*blockDim.x + threadIdx.x;
    int lane = i&31, ks = (i>>5)&3, tl = (i>>7)&7, dc = (i>>10)&7, mb = i>>13;
    int gr = lane>>2, gc = lane&3;
    int r0 = (mb*8+tl)*16 + gr, c0 = (dc*4+ks)*8 + gc;
    float4 v;
    v.x = tf32r(src[(size_t)r0*DD + c0]);
    v.y = tf32r(src[(size_t)(r0+8)*DD + c0]);
    v.z = tf32r(src[(size_t)r0*DD + c0+4]);
    v.w = tf32r(src[(size_t)(r0+8)*DD + c0+4]);
    dst[i] = v;
}
// ---- prep: pack B ([nt][dc] 32KB blocks, n8-tiles paired for LDS.128) ----
__global__ void packB(const float* __restrict__ src, float2* __restrict__ dst){
    int i = blockIdx.x*blockDim.x + threadIdx.x;
    int lane = i&31, ks = (i>>5)&3, ntl = (i>>7)&31, dc = (i>>12)&7, nt = i>>15;
    int gr = lane>>2, gc = lane&3;
    int r = (nt*32+ntl)*8 + gr, c0 = (dc*4+ks)*8 + gc;
    float2 v;
    v.x = tf32r(src[(size_t)r*DD + c0]);
    v.y = tf32r(src[(size_t)r*DD + c0+4]);
    size_t blk = (size_t)(nt*8+dc)*32768;
    size_t off = blk + ((((size_t)(ntl>>1)*4+ks)*32+lane)<<4) + ((ntl&1)<<3);
    dst[off>>3] = v;
}
__global__ void sumsq_kernel(const float* __restrict__ x, float* __restrict__ o, int rows){
    if(blockIdx.x==0 && threadIdx.x==0) g_cnt = 0;
    int row = blockIdx.x*(blockDim.x>>5) + (threadIdx.x>>5); if(row>=rows) return;
    int lane = threadIdx.x&31; const float* p = x + (size_t)row*DD; float s=0.f;
    #pragma unroll
    for(int c=lane;c<DD;c+=32){ float v=p[c]; s+=v*v; }
    #pragma unroll
    for(int ofs=16;ofs;ofs>>=1) s+=__shfl_down_sync(0xffffffffu,s,ofs);
    if(!lane) o[row]=s;
}

// ---- phase 1: A panel resident, 3-stage B pipeline, distributed producer ----
__global__ void __launch_bounds__(NTHR,1) vq_phase1(
    const float* __restrict__ E, const float* __restrict__ esq,
    float* __restrict__ outq, float* __restrict__ outi)
{
    extern __shared__ char smem[];
    const uint32_t sb = s2u(smem);
    const int tid = threadIdx.x, wid = tid>>5, lane = tid&31;
    const int r = lane>>2, c = lane&3;
    const int wm = wid&3, wn = wid>>2;     // 4x4 warp grid, warp tile 32x64
    const int mb = blockIdx.x, m0 = mb*BM;

    const uint32_t abar   = sb + BARS;          // A-panel barrier
    const uint32_t fullb  = sb + BARS + 16;     // 3 x 8B
    const uint32_t emptyb = sb + BARS + 64;     // 3 x 8B

    if(tid==0){
        MBAR_INIT(abar,1);
        #pragma unroll
        for(int s=0;s<NSTG;s++){ MBAR_INIT(fullb+s*8,1); MBAR_INIT(emptyb+s*8,16); }
    }
    __syncthreads();
    if(tid==0){
        MBAR_EXPECT_TX(abar, ASZ);
        BULK_G2S(sb, (const char*)g_xp + (size_t)mb*ASZ, ASZ, abar);
        #pragma unroll
        for(int j=0;j<NSTG;j++){
            MBAR_EXPECT_TX(fullb+j*8, BSTG);
            BULK_G2S(sb + BOFF + j*BSTG, (const char*)g_ep + (size_t)j*BSTG, BSTG, fullb+j*8);
        }
    }
    MBAR_WAIT(abar, 0);

    float m1[4], m2[4]; int i1[4];
    #pragma unroll
    for(int i=0;i<4;i++){ m1[i]=3.4e38f; m2[i]=3.4e38f; i1[i]=0; }

    for(int nt=0; nt<NNT; nt++){
        float acc[2][8][4];
        #pragma unroll
        for(int m=0;m<2;m++)
            #pragma unroll
            for(int n=0;n<8;n++){ acc[m][n][0]=0.f;acc[m][n][1]=0.f;acc[m][n][2]=0.f;acc[m][n][3]=0.f; }

        for(int dc=0; dc<8; dc++){
            const int j = nt*8 + dc;
            const int s = j - (j/3)*3;            // j % 3
            MBAR_WAIT(fullb+s*8, (j/3)&1);
            const char* stp = smem + BOFF + (size_t)s*BSTG;
            const char* sta = smem + (size_t)dc*16384;

            #pragma unroll
            for(int ks=0; ks<4; ks++){
                float4 af[2]; float4 bq[4];
                #pragma unroll
                for(int m=0;m<2;m++)
                    af[m] = *(const float4*)(sta + ((wm*2+m)*4+ks)*512 + lane*16);
                #pragma unroll
                for(int p=0;p<4;p++)
                    bq[p] = *(const float4*)(stp + ((wn*4+p)*4+ks)*512 + lane*16);
                #pragma unroll
                for(int m=0;m<2;m++)
                    #pragma unroll
                    for(int p=0;p<4;p++){
                        mma8(acc[m][2*p],   (const uint32_t*)&af[m], (const uint32_t*)&bq[p].x);
                        mma8(acc[m][2*p+1], (const uint32_t*)&af[m], (const uint32_t*)&bq[p].z);
                    }
            }
            __syncwarp();
            if(lane==0) MBAR_ARRIVE(emptyb+s*8);
            // distributed producer: warp (j&15) prefetches iter j+3
            if(wid == (j&15) && lane==0 && j+3 < NIT){
                const int jj = j+3;
                const int sj = jj - (jj/3)*3;
                MBAR_WAIT(emptyb+sj*8, ((jj/3)-1)&1);
                MBAR_EXPECT_TX(fullb+sj*8, BSTG);
                const int ntj = jj>>3, dcj = jj&7;
                BULK_G2S(sb + BOFF + sj*BSTG,
                         (const char*)g_ep + (size_t)(ntj*8+dcj)*BSTG, BSTG, fullb+sj*8);
            }
        }
        // fold this 256-col tile into running argmin (cols ascending)
        #pragma unroll
        for(int n=0;n<8;n++){
            int colb = nt*BN + wn*64 + n*8 + 2*c;
            float e0 = __ldg(esq+colb), e1 = __ldg(esq+colb+1);
            #pragma unroll
            for(int m=0;m<2;m++){
                const int rl=2*m, rh=2*m+1;
                float d;
                d = fmaf(-2.f, acc[m][n][0], e0);
                if(d<m1[rl]){m2[rl]=m1[rl];m1[rl]=d;i1[rl]=colb;} else if(d<m2[rl]) m2[rl]=d;
                d = fmaf(-2.f, acc[m][n][1], e1);
                if(d<m1[rl]){m2[rl]=m1[rl];m1[rl]=d;i1[rl]=colb+1;} else if(d<m2[rl]) m2[rl]=d;
                d = fmaf(-2.f, acc[m][n][2], e0);
                if(d<m1[rh]){m2[rh]=m1[rh];m1[rh]=d;i1[rh]=colb;} else if(d<m2[rh]) m2[rh]=d;
                d = fmaf(-2.f, acc[m][n][3], e1);
                if(d<m1[rh]){m2[rh]=m1[rh];m1[rh]=d;i1[rh]=colb+1;} else if(d<m2[rh]) m2[rh]=d;
            }
        }
    }

    // epilogue reduction overlays the (now dead) B stage buffers
    float* s_m1 = (float*)(smem + BOFF);
    float* s_m2 = (float*)(smem + BOFF + 8192);
    int*   s_i1 = (int*)(smem + BOFF + 16384);
    int*   s_idx= (int*)(smem + BOFF + 24576);
    __syncthreads();
    #pragma unroll
    for(int i=0;i<4;i++){
        int row  = wm*32 + (i>>1)*16 + r + (i&1)*8;
        int slot = wn*4 + c;
        s_m1[row*16+slot] = m1[i];
        s_m2[row*16+slot] = m2[i];
        s_i1[row*16+slot] = i1[i];
    }
    __syncthreads();
    if(tid < 128){
        float bd = 3.4e38f; int bi = 0, tw = 0;
        #pragma unroll
        for(int t=0;t<16;t++){
            float d = s_m1[tid*16+t]; int ii = s_i1[tid*16+t];
            if(d<bd || (d==bd && ii<bi)){ bd=d; bi=ii; tw=t; }
        }
        float b2 = 3.4e38f;
        #pragma unroll
        for(int t=0;t<16;t++){
            float v = (t==tw) ? s_m2[tid*16+t] : s_m1[tid*16+t];
            b2 = fminf(b2, v);
        }
        s_idx[tid] = bi;
        outi[m0+tid] = (float)bi;
        if(b2 - bd < FLAG_T){
            g_best[m0+tid] = 0xFFFFFFFFFFFFFFFFull;
            int pos = atomicAdd(&g_cnt, 1);
            if(pos < FLAG_CAP) g_flag[pos] = m0 + tid;
        }
    }
    __syncthreads();
    for(int f=tid; f<BM*(DD/4); f+=NTHR){
        int rr = f>>6, c4 = f&63;
        float4 v = *(const float4*)(E + (size_t)s_idx[rr]*DD + c4*4);
        *(float4*)(outq + (size_t)(m0+rr)*DD + c4*4) = v;
    }
}

// ---- phase 2: exact fp32 rescore, K-split, atomicMin merge ----
__global__ void __launch_bounds__(128) vq_phase2(
    const float* __restrict__ X, const float* __restrict__ E, const float* __restrict__ esq)
{
    int cnt = g_cnt; if(cnt > FLAG_CAP) cnt = FLAG_CAP;
    const int rb = blockIdx.x;
    if(rb*P2M >= cnt) return;
    const int k0 = blockIdx.y * 128;
    __shared__ float Xs[16][P2M];
    __shared__ float Es[16][128];
    __shared__ int rows[P2M];
    __shared__ float s_bd[16][P2M];
    __shared__ int   s_bi[16][P2M];
    const int tid = threadIdx.x;
    const int tx = tid&15, ty = tid>>4;
    if(tid < P2M){
        int fi = rb*P2M + tid; if(fi >= cnt) fi = cnt-1;
        rows[tid] = g_flag[fi];
    }
    __syncthreads();

    float acc[8][8];
    #pragma unroll
    for(int i=0;i<8;i++)
        #pragma unroll
        for(int j=0;j<8;j++) acc[i][j]=0.f;

    for(int d0=0; d0<DD; d0+=16){
        #pragma unroll
        for(int l=0;l<2;l++){
            int f = tid + l*128, rr = f>>2, c4 = f&3;
            float4 v = *(const float4*)(X + (size_t)rows[rr]*DD + d0 + c4*4);
            Xs[c4*4+0][rr]=v.x; Xs[c4*4+1][rr]=v.y; Xs[c4*4+2][rr]=v.z; Xs[c4*4+3][rr]=v.w;
        }
        #pragma unroll
        for(int l=0;l<4;l++){
            int f = tid + l*128, rr = f>>2, c4 = f&3;
            float4 v = *(const float4*)(E + (size_t)(k0+rr)*DD + d0 + c4*4);
            Es[c4*4+0][rr]=v.x; Es[c4*4+1][rr]=v.y; Es[c4*4+2][rr]=v.z; Es[c4*4+3][rr]=v.w;
        }
        __syncthreads();
        #pragma unroll
        for(int kk=0;kk<16;kk++){
            float xr[8], er[8];
            #pragma unroll
            for(int i=0;i<8;i++) xr[i]=Xs[kk][ty*8+i];
            #pragma unroll
            for(int j=0;j<8;j++) er[j]=Es[kk][tx*8+j];
            #pragma unroll
            for(int i=0;i<8;i++)
                #pragma unroll
                for(int j=0;j<8;j++) acc[i][j]=fmaf(xr[i],er[j],acc[i][j]);
        }
        __syncthreads();
    }
    float bd[8]; int bi[8];
    #pragma unroll
    for(int i=0;i<8;i++){ bd[i]=3.4e38f; bi[i]=0; }
    #pragma unroll
    for(int i=0;i<8;i++)
        #pragma unroll
        for(int j=0;j<8;j++){
            int col = k0 + tx*8 + j;
            float d = __ldg(esq+col) - 2.f*acc[i][j];
            if(d < bd[i]){ bd[i]=d; bi[i]=col; }
        }
    #pragma unroll
    for(int i=0;i<8;i++){ s_bd[tx][ty*8+i]=bd[i]; s_bi[tx][ty*8+i]=bi[i]; }
    __syncthreads();
    if(tid < P2M){
        float b = s_bd[0][tid]; int ii = s_bi[0][tid];
        #pragma unroll
        for(int t=1;t<16;t++){
            float d = s_bd[t][tid]; int jj = s_bi[t][tid];
            if(d<b || (d==b && jj<ii)){ b=d; ii=jj; }
        }
        if(rb*P2M + tid < cnt){
            uint32_t u = __float_as_uint(b);
            u = (u & 0x80000000u) ? ~u : (u | 0x80000000u);
            unsigned long long key = ((unsigned long long)u << 32) | (unsigned)ii;
            atomicMin(&g_best[rows[tid]], key);
        }
    }
}

// ---- phase 3: write back flagged rows ----
__global__ void __launch_bounds__(256) vq_phase3(
    const float* __restrict__ E, float* __restrict__ outq, float* __restrict__ outi)
{
    int cnt = g_cnt; if(cnt > FLAG_CAP) cnt = FLAG_CAP;
    int i = blockIdx.x*8 + (threadIdx.x>>5);
    if(i >= cnt) return;
    int lane = threadIdx.x&31;
    int row = g_flag[i];
    int bi = (int)(g_best[row] & 0xFFFFFFFFull);
    if(lane==0) outi[row] = (float)bi;
    float4 v0 = *(const float4*)(E + (size_t)bi*DD + lane*8);
    float4 v1 = *(const float4*)(E + (size_t)bi*DD + lane*8 + 4);
    *(float4*)(outq + (size_t)row*DD + lane*8)     = v0;
    *(float4*)(outq + (size_t)row*DD + lane*8 + 4) = v1;
}

extern "C" void kernel_launch(void* const* d_in, const int* in_sizes, int n_in,
                              void* d_out, int out_size) {
    const float* X = (const float*)d_in[0];
    const float* E = (const float*)d_in[1];

    float4* xp; float2* ep; float* esq;
    cudaGetSymbolAddress((void**)&xp, g_xp);
    cudaGetSymbolAddress((void**)&ep, g_ep);
    cudaGetSymbolAddress((void**)&esq, g_esq);

    packA<<<NTOK*DD/4/256, 256>>>(X, xp);
    packB<<<KCB*DD/2/256, 256>>>(E, ep);
    sumsq_kernel<<<KCB/8, 256>>>(E, esq, KCB);   // also zeroes g_cnt

    float* outq = (float*)d_out;
    float* outi = (float*)d_out + (size_t)NTOK*DD;

    cudaFuncSetAttribute(vq_phase1, cudaFuncAttributeMaxDynamicSharedMemorySize, SMEMSZ);
    vq_phase1<<<NMB, NTHR, SMEMSZ>>>(E, esq, outq, outi);
    vq_phase2<<<dim3(FLAG_CAP/P2M, KCB/128), 128>>>(X, E, esq);
    vq_phase3<<<FLAG_CAP/8, 256>>>(E, outq, outi);
}

// round 12
// speedup vs baseline: 1.5230x; 1.3813x over previous
#include <cuda_runtime.h>
#include <cuda_fp16.h>
#include <cstdint>

#define DD 256
#define NTOK 16384
#define KCB 8192
#define BM 128
#define BN 256
#define NMB (NTOK/BM)     // 128
#define NNT (KCB/BN)      // 32
#define NIT (NNT*8)       // 256
#define ASZ 65536         // A panel: 8 dc x 8KB (fp16)
#define BSTG 16384        // B stage (fp16)
#define NSTG 5
#define BOFF ASZ
#define BARS (ASZ + NSTG*BSTG)   // 147456
#define SMEMSZ (BARS + 256)
#define NTHR 512
#define FLAG_T 0.12f
#define FLAG_CAP 4096
#define P2M 64

// A packed fp16: [mb][dc] -> 8KB ([tl 8][ks 2][lane 32] x 16B)
__device__ __align__(128) uint4 g_xp[NTOK*DD*2/16];
// B packed fp16: [nt][dc] -> 16KB ([pair 16][ks 2][lane 32] x 16B)
__device__ __align__(128) uint2 g_ep[KCB*DD*2/8];
__device__ __align__(128) float g_esq[KCB];
__device__ unsigned long long g_best[NTOK];
__device__ int g_flag[FLAG_CAP];
__device__ int g_cnt;

__device__ __forceinline__ uint32_t s2u(const void* p){
    uint32_t a; asm("{ .reg .u64 t; cvta.to.shared.u64 t, %1; cvt.u32.u64 %0, t; }":"=r"(a):"l"(p)); return a;
}
#define MBAR_INIT(a,c) asm volatile("mbarrier.init.shared.b64 [%0], %1;"::"r"(a),"r"(c):"memory")
#define MBAR_ARRIVE(a) asm volatile("mbarrier.arrive.shared.b64 _, [%0];"::"r"(a):"memory")
#define MBAR_EXPECT_TX(a,tx) asm volatile("mbarrier.arrive.expect_tx.shared.b64 _, [%0], %1;"::"r"(a),"r"(tx):"memory")
#define MBAR_WAIT(a,p) do{ uint32_t _m=(a),_p=(p),_d; \
    asm volatile("{\n\t.reg .pred q;\n\tmbarrier.try_wait.parity.acquire.cta.shared::cta.b64 q,[%1],%2;\n\tselp.b32 %0,1,0,q;\n\t}":"=r"(_d):"r"(_m),"r"(_p):"memory"); \
    if(!_d){ asm volatile("{\n\t.reg .pred q;\n\tW%=:\n\tmbarrier.try_wait.parity.acquire.cta.shared::cta.b64 q,[%0],%1,0x989680;\n\t@q bra.uni DN%=;\n\tbra.uni W%=;\n\tDN%=:\n\t}"::"r"(_m),"r"(_p):"memory"); } }while(0)
#define BULK_G2S(d,s,n,mb) asm volatile( \
    "cp.async.bulk.shared::cluster.global.mbarrier::complete_tx::bytes [%0], [%1], %2, [%3];" \
    :: "r"((uint32_t)(d)),"l"(s),"r"((uint32_t)(n)),"r"((uint32_t)(mb)) : "memory")

__device__ __forceinline__ void mma16(float* d, const uint32_t* a, const uint32_t* b){
    asm("mma.sync.aligned.m16n8k16.row.col.f32.f16.f16.f32 "
        "{%0,%1,%2,%3}, {%4,%5,%6,%7}, {%8,%9}, {%0,%1,%2,%3};"
        : "+f"(d[0]),"+f"(d[1]),"+f"(d[2]),"+f"(d[3])
        : "r"(a[0]),"r"(a[1]),"r"(a[2]),"r"(a[3]),"r"(b[0]),"r"(b[1]));
}

// ---- prep: pack A fp16 fragments ----
__global__ void packA(const float* __restrict__ src, uint4* __restrict__ dst){
    int i = blockIdx.x*blockDim.x + threadIdx.x;   // 524288
    int lane = i&31, ks = (i>>5)&1, tl = (i>>6)&7, dc = (i>>9)&7, mb = i>>12;
    int gr = lane>>2, t = lane&3;
    int r0 = (mb*8+tl)*16 + gr;
    int k0 = dc*32 + ks*16 + 2*t;
    const float* p0 = src + (size_t)r0*DD;
    const float* p1 = src + (size_t)(r0+8)*DD;
    __half h[8];
    h[0]=__float2half_rn(p0[k0]);   h[1]=__float2half_rn(p0[k0+1]);
    h[2]=__float2half_rn(p1[k0]);   h[3]=__float2half_rn(p1[k0+1]);
    h[4]=__float2half_rn(p0[k0+8]); h[5]=__float2half_rn(p0[k0+9]);
    h[6]=__float2half_rn(p1[k0+8]); h[7]=__float2half_rn(p1[k0+9]);
    dst[i] = *(const uint4*)h;
}
// ---- prep: pack B fp16 fragments (n8-tiles paired for LDS.128) ----
__global__ void packB(const float* __restrict__ src, uint2* __restrict__ dst){
    int i = blockIdx.x*blockDim.x + threadIdx.x;   // 524288
    int lane = i&31, ks = (i>>5)&1, ntl = (i>>6)&31, dc = (i>>11)&7, nt = i>>14;
    int gr = lane>>2, t = lane&3;
    int col = nt*BN + ntl*8 + gr;
    int k0 = dc*32 + ks*16 + 2*t;
    const float* p = src + (size_t)col*DD;
    __half h[4];
    h[0]=__float2half_rn(p[k0]);   h[1]=__float2half_rn(p[k0+1]);
    h[2]=__float2half_rn(p[k0+8]); h[3]=__float2half_rn(p[k0+9]);
    size_t blk = (size_t)(nt*8+dc)*16384;
    size_t off = blk + ((((size_t)(ntl>>1)*2+ks)*32+lane)<<4) + ((ntl&1)<<3);
    dst[off>>3] = *(const uint2*)h;
}
__global__ void sumsq_kernel(const float* __restrict__ x, float* __restrict__ o, int rows){
    if(blockIdx.x==0 && threadIdx.x==0) g_cnt = 0;
    int row = blockIdx.x*(blockDim.x>>5) + (threadIdx.x>>5); if(row>=rows) return;
    int lane = threadIdx.x&31; const float* p = x + (size_t)row*DD; float s=0.f;
    #pragma unroll
    for(int c=lane;c<DD;c+=32){ float v=p[c]; s+=v*v; }
    #pragma unroll
    for(int ofs=16;ofs;ofs>>=1) s+=__shfl_down_sync(0xffffffffu,s,ofs);
    if(!lane) o[row]=s;
}

// ---- phase 1: fp16 single-pass GEMM, A panel resident, 5-stage B pipeline ----
__global__ void __launch_bounds__(NTHR,1) vq_phase1(
    const float* __restrict__ E, const float* __restrict__ esq,
    float* __restrict__ outq, float* __restrict__ outi)
{
    extern __shared__ char smem[];
    const uint32_t sb = s2u(smem);
    const int tid = threadIdx.x, wid = tid>>5, lane = tid&31;
    const int r = lane>>2, c = lane&3;
    const int wm = wid&3, wn = wid>>2;     // 4x4 warp grid, warp tile 32x64
    const int mb = blockIdx.x, m0 = mb*BM;

    const uint32_t abar   = sb + BARS;
    const uint32_t fullb  = sb + BARS + 16;
    const uint32_t emptyb = sb + BARS + 72;

    if(tid==0){
        MBAR_INIT(abar,1);
        #pragma unroll
        for(int s=0;s<NSTG;s++){ MBAR_INIT(fullb+s*8,1); MBAR_INIT(emptyb+s*8,16); }
    }
    __syncthreads();
    if(tid==0){
        MBAR_EXPECT_TX(abar, ASZ);
        BULK_G2S(sb, (const char*)g_xp + (size_t)mb*ASZ, ASZ, abar);
        #pragma unroll
        for(int j=0;j<NSTG-1;j++){
            MBAR_EXPECT_TX(fullb+j*8, BSTG);
            BULK_G2S(sb + BOFF + j*BSTG, (const char*)g_ep + (size_t)j*BSTG, BSTG, fullb+j*8);
        }
    }
    MBAR_WAIT(abar, 0);

    float m1[4], m2[4]; int i1[4];
    #pragma unroll
    for(int i=0;i<4;i++){ m1[i]=3.4e38f; m2[i]=3.4e38f; i1[i]=0; }

    for(int nt=0; nt<NNT; nt++){
        float acc[2][8][4];
        #pragma unroll
        for(int m=0;m<2;m++)
            #pragma unroll
            for(int n=0;n<8;n++){ acc[m][n][0]=0.f;acc[m][n][1]=0.f;acc[m][n][2]=0.f;acc[m][n][3]=0.f; }

        for(int dc=0; dc<8; dc++){
            const int j = nt*8 + dc;
            const int s = j - (j/NSTG)*NSTG;       // j % 5
            MBAR_WAIT(fullb+s*8, (j/NSTG)&1);
            const char* stp = smem + BOFF + (size_t)s*BSTG;
            const char* sta = smem + (size_t)dc*8192;

            #pragma unroll
            for(int ks=0; ks<2; ks++){
                uint4 af[2]; uint4 bq[4];
                #pragma unroll
                for(int m=0;m<2;m++)
                    af[m] = *(const uint4*)(sta + (((wm*2+m)*2+ks)*32+lane)*16);
                #pragma unroll
                for(int p=0;p<4;p++)
                    bq[p] = *(const uint4*)(stp + (((wn*4+p)*2+ks)*32+lane)*16);
                #pragma unroll
                for(int m=0;m<2;m++)
                    #pragma unroll
                    for(int p=0;p<4;p++){
                        mma16(acc[m][2*p],   (const uint32_t*)&af[m], &bq[p].x);
                        mma16(acc[m][2*p+1], (const uint32_t*)&af[m], &bq[p].z);
                    }
            }
            __syncwarp();
            if(lane==0) MBAR_ARRIVE(emptyb+s*8);
            // distributed producer: warp (j&15) lane0 prefetches iter j+NSTG-1
            if(wid == (j&15) && lane==0 && j+NSTG-1 < NIT){
                const int jj = j+NSTG-1;
                const int sj = jj - (jj/NSTG)*NSTG;
                if(jj >= NSTG) MBAR_WAIT(emptyb+sj*8, ((jj/NSTG)-1)&1);
                MBAR_EXPECT_TX(fullb+sj*8, BSTG);
                const int ntj = jj>>3, dcj = jj&7;
                BULK_G2S(sb + BOFF + sj*BSTG,
                         (const char*)g_ep + (size_t)(ntj*8+dcj)*BSTG, BSTG, fullb+sj*8);
            }
        }
        // fold this 256-col tile into running argmin (cols ascending)
        #pragma unroll
        for(int n=0;n<8;n++){
            int colb = nt*BN + wn*64 + n*8 + 2*c;
            float e0 = __ldg(esq+colb), e1 = __ldg(esq+colb+1);
            #pragma unroll
            for(int m=0;m<2;m++){
                const int rl=2*m, rh=2*m+1;
                float d;
                d = fmaf(-2.f, acc[m][n][0], e0);
                if(d<m1[rl]){m2[rl]=m1[rl];m1[rl]=d;i1[rl]=colb;} else if(d<m2[rl]) m2[rl]=d;
                d = fmaf(-2.f, acc[m][n][1], e1);
                if(d<m1[rl]){m2[rl]=m1[rl];m1[rl]=d;i1[rl]=colb+1;} else if(d<m2[rl]) m2[rl]=d;
                d = fmaf(-2.f, acc[m][n][2], e0);
                if(d<m1[rh]){m2[rh]=m1[rh];m1[rh]=d;i1[rh]=colb;} else if(d<m2[rh]) m2[rh]=d;
                d = fmaf(-2.f, acc[m][n][3], e1);
                if(d<m1[rh]){m2[rh]=m1[rh];m1[rh]=d;i1[rh]=colb+1;} else if(d<m2[rh]) m2[rh]=d;
            }
        }
    }

    // epilogue reduction overlays the (now dead) B stage buffers
    float* s_m1 = (float*)(smem + BOFF);
    float* s_m2 = (float*)(smem + BOFF + 8192);
    int*   s_i1 = (int*)(smem + BOFF + 16384);
    int*   s_idx= (int*)(smem + BOFF + 24576);
    __syncthreads();
    #pragma unroll
    for(int i=0;i<4;i++){
        int row  = wm*32 + (i>>1)*16 + r + (i&1)*8;
        int slot = wn*4 + c;
        s_m1[row*16+slot] = m1[i];
        s_m2[row*16+slot] = m2[i];
        s_i1[row*16+slot] = i1[i];
    }
    __syncthreads();
    if(tid < 128){
        float bd = 3.4e38f; int bi = 0, tw = 0;
        #pragma unroll
        for(int t=0;t<16;t++){
            float d = s_m1[tid*16+t]; int ii = s_i1[tid*16+t];
            if(d<bd || (d==bd && ii<bi)){ bd=d; bi=ii; tw=t; }
        }
        float b2 = 3.4e38f;
        #pragma unroll
        for(int t=0;t<16;t++){
            float v = (t==tw) ? s_m2[tid*16+t] : s_m1[tid*16+t];
            b2 = fminf(b2, v);
        }
        s_idx[tid] = bi;
        outi[m0+tid] = (float)bi;
        if(b2 - bd < FLAG_T){
            g_best[m0+tid] = 0xFFFFFFFFFFFFFFFFull;
            int pos = atomicAdd(&g_cnt, 1);
            if(pos < FLAG_CAP) g_flag[pos] = m0 + tid;
        }
    }
    __syncthreads();
    for(int f=tid; f<BM*(DD/4); f+=NTHR){
        int rr = f>>6, c4 = f&63;
        float4 v = *(const float4*)(E + (size_t)s_idx[rr]*DD + c4*4);
        *(float4*)(outq + (size_t)(m0+rr)*DD + c4*4) = v;
    }
}

// ---- phase 2: exact fp32 rescore, K-split, atomicMin merge ----
__global__ void __launch_bounds__(128) vq_phase2(
    const float* __restrict__ X, const float* __restrict__ E, const float* __restrict__ esq)
{
    int cnt = g_cnt; if(cnt > FLAG_CAP) cnt = FLAG_CAP;
    const int rb = blockIdx.x;
    if(rb*P2M >= cnt) return;
    const int k0 = blockIdx.y * 128;
    __shared__ float Xs[16][P2M];
    __shared__ float Es[16][128];
    __shared__ int rows[P2M];
    __shared__ float s_bd[16][P2M];
    __shared__ int   s_bi[16][P2M];
    const int tid = threadIdx.x;
    const int tx = tid&15, ty = tid>>4;
    if(tid < P2M){
        int fi = rb*P2M + tid; if(fi >= cnt) fi = cnt-1;
        rows[tid] = g_flag[fi];
    }
    __syncthreads();

    float acc[8][8];
    #pragma unroll
    for(int i=0;i<8;i++)
        #pragma unroll
        for(int j=0;j<8;j++) acc[i][j]=0.f;

    for(int d0=0; d0<DD; d0+=16){
        #pragma unroll
        for(int l=0;l<2;l++){
            int f = tid + l*128, rr = f>>2, c4 = f&3;
            float4 v = *(const float4*)(X + (size_t)rows[rr]*DD + d0 + c4*4);
            Xs[c4*4+0][rr]=v.x; Xs[c4*4+1][rr]=v.y; Xs[c4*4+2][rr]=v.z; Xs[c4*4+3][rr]=v.w;
        }
        #pragma unroll
        for(int l=0;l<4;l++){
            int f = tid + l*128, rr = f>>2, c4 = f&3;
            float4 v = *(const float4*)(E + (size_t)(k0+rr)*DD + d0 + c4*4);
            Es[c4*4+0][rr]=v.x; Es[c4*4+1][rr]=v.y; Es[c4*4+2][rr]=v.z; Es[c4*4+3][rr]=v.w;
        }
        __syncthreads();
        #pragma unroll
        for(int kk=0;kk<16;kk++){
            float xr[8], er[8];
            #pragma unroll
            for(int i=0;i<8;i++) xr[i]=Xs[kk][ty*8+i];
            #pragma unroll
            for(int j=0;j<8;j++) er[j]=Es[kk][tx*8+j];
            #pragma unroll
            for(int i=0;i<8;i++)
                #pragma unroll
                for(int j=0;j<8;j++) acc[i][j]=fmaf(xr[i],er[j],acc[i][j]);
        }
        __syncthreads();
    }
    float bd[8]; int bi[8];
    #pragma unroll
    for(int i=0;i<8;i++){ bd[i]=3.4e38f; bi[i]=0; }
    #pragma unroll
    for(int i=0;i<8;i++)
        #pragma unroll
        for(int j=0;j<8;j++){
            int col = k0 + tx*8 + j;
            float d = __ldg(esq+col) - 2.f*acc[i][j];
            if(d < bd[i]){ bd[i]=d; bi[i]=col; }
        }
    #pragma unroll
    for(int i=0;i<8;i++){ s_bd[tx][ty*8+i]=bd[i]; s_bi[tx][ty*8+i]=bi[i]; }
    __syncthreads();
    if(tid < P2M){
        float b = s_bd[0][tid]; int ii = s_bi[0][tid];
        #pragma unroll
        for(int t=1;t<16;t++){
            float d = s_bd[t][tid]; int jj = s_bi[t][tid];
            if(d<b || (d==b && jj<ii)){ b=d; ii=jj; }
        }
        if(rb*P2M + tid < cnt){
            uint32_t u = __float_as_uint(b);
            u = (u & 0x80000000u) ? ~u : (u | 0x80000000u);
            unsigned long long key = ((unsigned long long)u << 32) | (unsigned)ii;
            atomicMin(&g_best[rows[tid]], key);
        }
    }
}

// ---- phase 3: write back flagged rows ----
__global__ void __launch_bounds__(256) vq_phase3(
    const float* __restrict__ E, float* __restrict__ outq, float* __restrict__ outi)
{
    int cnt = g_cnt; if(cnt > FLAG_CAP) cnt = FLAG_CAP;
    int i = blockIdx.x*8 + (threadIdx.x>>5);
    if(i >= cnt) return;
    int lane = threadIdx.x&31;
    int row = g_flag[i];
    int bi = (int)(g_best[row] & 0xFFFFFFFFull);
    if(lane==0) outi[row] = (float)bi;
    float4 v0 = *(const float4*)(E + (size_t)bi*DD + lane*8);
    float4 v1 = *(const float4*)(E + (size_t)bi*DD + lane*8 + 4);
    *(float4*)(outq + (size_t)row*DD + lane*8)     = v0;
    *(float4*)(outq + (size_t)row*DD + lane*8 + 4) = v1;
}

extern "C" void kernel_launch(void* const* d_in, const int* in_sizes, int n_in,
                              void* d_out, int out_size) {
    const float* X = (const float*)d_in[0];
    const float* E = (const float*)d_in[1];

    uint4* xp; uint2* ep; float* esq;
    cudaGetSymbolAddress((void**)&xp, g_xp);
    cudaGetSymbolAddress((void**)&ep, g_ep);
    cudaGetSymbolAddress((void**)&esq, g_esq);

    packA<<<NTOK*DD*2/16/256, 256>>>(X, xp);
    packB<<<KCB*DD*2/8/256, 256>>>(E, ep);
    sumsq_kernel<<<KCB/8, 256>>>(E, esq, KCB);   // also zeroes g_cnt

    float* outq = (float*)d_out;
    float* outi = (float*)d_out + (size_t)NTOK*DD;

    cudaFuncSetAttribute(vq_phase1, cudaFuncAttributeMaxDynamicSharedMemorySize, SMEMSZ);
    vq_phase1<<<NMB, NTHR, SMEMSZ>>>(E, esq, outq, outi);
    vq_phase2<<<dim3(FLAG_CAP/P2M, KCB/128), 128>>>(X, E, esq);
    vq_phase3<<<FLAG_CAP/8, 256>>>(E, outq, outi);
}

// round 13
// speedup vs baseline: 1.8133x; 1.1906x over previous
#include <cuda_runtime.h>
#include <cuda_fp16.h>
#include <cstdint>

#define DD 256
#define NTOK 16384
#define KCB 8192
#define BM 64
#define BN 256
#define NMB (NTOK/BM)     // 256
#define NNT (KCB/BN)      // 32
#define NIT (NNT*8)       // 256
#define ASZ 32768         // A panel: 8 dc x 4KB (fp16, 64 rows)
#define BSTG 16384
#define NSTG 4
#define BOFF ASZ
#define BARS (ASZ + NSTG*BSTG)   // 98304
#define SMEMSZ (BARS + 256)
#define NTHR 256
#define FLAG_T 0.12f
#define FLAG_CAP 4096
#define P2M 64

// A packed fp16: [mb 256][dc 8] -> 4KB ([tl 4][ks 2][lane 32] x 16B)
__device__ __align__(128) uint4 g_xp[NTOK*DD*2/16];
// B packed fp16: [nt][dc] -> 16KB ([pair 16][ks 2][lane 32] x 16B)
__device__ __align__(128) uint2 g_ep[KCB*DD*2/8];
__device__ __align__(128) float g_esq[KCB];
__device__ unsigned long long g_best[NTOK];
__device__ int g_flag[FLAG_CAP];
__device__ int g_cnt;

__device__ __forceinline__ uint32_t s2u(const void* p){
    uint32_t a; asm("{ .reg .u64 t; cvta.to.shared.u64 t, %1; cvt.u32.u64 %0, t; }":"=r"(a):"l"(p)); return a;
}
#define MBAR_INIT(a,c) asm volatile("mbarrier.init.shared.b64 [%0], %1;"::"r"(a),"r"(c):"memory")
#define MBAR_ARRIVE(a) asm volatile("mbarrier.arrive.shared.b64 _, [%0];"::"r"(a):"memory")
#define MBAR_EXPECT_TX(a,tx) asm volatile("mbarrier.arrive.expect_tx.shared.b64 _, [%0], %1;"::"r"(a),"r"(tx):"memory")
#define MBAR_WAIT(a,p) do{ uint32_t _m=(a),_p=(p),_d; \
    asm volatile("{\n\t.reg .pred q;\n\tmbarrier.try_wait.parity.acquire.cta.shared::cta.b64 q,[%1],%2;\n\tselp.b32 %0,1,0,q;\n\t}":"=r"(_d):"r"(_m),"r"(_p):"memory"); \
    if(!_d){ asm volatile("{\n\t.reg .pred q;\n\tW%=:\n\tmbarrier.try_wait.parity.acquire.cta.shared::cta.b64 q,[%0],%1,0x989680;\n\t@q bra.uni DN%=;\n\tbra.uni W%=;\n\tDN%=:\n\t}"::"r"(_m),"r"(_p):"memory"); } }while(0)
#define BULK_G2S(d,s,n,mb) asm volatile( \
    "cp.async.bulk.shared::cluster.global.mbarrier::complete_tx::bytes [%0], [%1], %2, [%3];" \
    :: "r"((uint32_t)(d)),"l"(s),"r"((uint32_t)(n)),"r"((uint32_t)(mb)) : "memory")

__device__ __forceinline__ void mma16(float* d, const uint32_t* a, const uint32_t* b){
    asm("mma.sync.aligned.m16n8k16.row.col.f32.f16.f16.f32 "
        "{%0,%1,%2,%3}, {%4,%5,%6,%7}, {%8,%9}, {%0,%1,%2,%3};"
        : "+f"(d[0]),"+f"(d[1]),"+f"(d[2]),"+f"(d[3])
        : "r"(a[0]),"r"(a[1]),"r"(a[2]),"r"(a[3]),"r"(b[0]),"r"(b[1]));
}

// ---- prep: pack A fp16 fragments ([mb 256][dc 8][tl 4][ks 2][lane 32]) ----
__global__ void packA(const float* __restrict__ src, uint4* __restrict__ dst){
    int i = blockIdx.x*blockDim.x + threadIdx.x;   // 524288
    int lane = i&31, ks = (i>>5)&1, tl = (i>>6)&3, dc = (i>>8)&7, mb = i>>11;
    int gr = lane>>2, t = lane&3;
    int r0 = (mb*4+tl)*16 + gr;
    int k0 = dc*32 + ks*16 + 2*t;
    const float* p0 = src + (size_t)r0*DD;
    const float* p1 = src + (size_t)(r0+8)*DD;
    __half h[8];
    h[0]=__float2half_rn(p0[k0]);   h[1]=__float2half_rn(p0[k0+1]);
    h[2]=__float2half_rn(p1[k0]);   h[3]=__float2half_rn(p1[k0+1]);
    h[4]=__float2half_rn(p0[k0+8]); h[5]=__float2half_rn(p0[k0+9]);
    h[6]=__float2half_rn(p1[k0+8]); h[7]=__float2half_rn(p1[k0+9]);
    dst[i] = *(const uint4*)h;
}
// ---- prep: pack B fp16 fragments (n8-tiles paired for LDS.128) ----
__global__ void packB(const float* __restrict__ src, uint2* __restrict__ dst){
    int i = blockIdx.x*blockDim.x + threadIdx.x;   // 524288
    int lane = i&31, ks = (i>>5)&1, ntl = (i>>6)&31, dc = (i>>11)&7, nt = i>>14;
    int gr = lane>>2, t = lane&3;
    int col = nt*BN + ntl*8 + gr;
    int k0 = dc*32 + ks*16 + 2*t;
    const float* p = src + (size_t)col*DD;
    __half h[4];
    h[0]=__float2half_rn(p[k0]);   h[1]=__float2half_rn(p[k0+1]);
    h[2]=__float2half_rn(p[k0+8]); h[3]=__float2half_rn(p[k0+9]);
    size_t blk = (size_t)(nt*8+dc)*16384;
    size_t off = blk + ((((size_t)(ntl>>1)*2+ks)*32+lane)<<4) + ((ntl&1)<<3);
    dst[off>>3] = *(const uint2*)h;
}
__global__ void sumsq_kernel(const float* __restrict__ x, float* __restrict__ o, int rows){
    if(blockIdx.x==0 && threadIdx.x==0) g_cnt = 0;
    int row = blockIdx.x*(blockDim.x>>5) + (threadIdx.x>>5); if(row>=rows) return;
    int lane = threadIdx.x&31; const float* p = x + (size_t)row*DD; float s=0.f;
    #pragma unroll
    for(int c=lane;c<DD;c+=32){ float v=p[c]; s+=v*v; }
    #pragma unroll
    for(int ofs=16;ofs;ofs>>=1) s+=__shfl_down_sync(0xffffffffu,s,ofs);
    if(!lane) o[row]=s;
}

// ---- phase 1: BM=64, 2 CTAs/SM, fp16 GEMM, branchless argmin fold ----
__global__ void __launch_bounds__(NTHR,2) vq_phase1(
    const float* __restrict__ E, const float* __restrict__ esq,
    float* __restrict__ outq, float* __restrict__ outi)
{
    extern __shared__ char smem[];
    const uint32_t sb = s2u(smem);
    const int tid = threadIdx.x, wid = tid>>5, lane = tid&31;
    const int r = lane>>2, c = lane&3;
    const int wm = wid&1, wn = wid>>1;     // 2x4 warp grid, warp tile 32x64
    const int mb = blockIdx.x, m0 = mb*BM;

    const uint32_t abar   = sb + BARS;
    const uint32_t fullb  = sb + BARS + 16;
    const uint32_t emptyb = sb + BARS + 64;

    if(tid==0){
        MBAR_INIT(abar,1);
        #pragma unroll
        for(int s=0;s<NSTG;s++){ MBAR_INIT(fullb+s*8,1); MBAR_INIT(emptyb+s*8,8); }
    }
    __syncthreads();
    if(tid==0){
        MBAR_EXPECT_TX(abar, ASZ);
        BULK_G2S(sb, (const char*)g_xp + (size_t)mb*ASZ, ASZ, abar);
        #pragma unroll
        for(int j=0;j<NSTG-1;j++){
            MBAR_EXPECT_TX(fullb+j*8, BSTG);
            BULK_G2S(sb + BOFF + j*BSTG, (const char*)g_ep + (size_t)j*BSTG, BSTG, fullb+j*8);
        }
    }
    MBAR_WAIT(abar, 0);

    float m1[4], m2[4]; int i1[4];
    #pragma unroll
    for(int i=0;i<4;i++){ m1[i]=3.4e38f; m2[i]=3.4e38f; i1[i]=0; }

    for(int nt=0; nt<NNT; nt++){
        float acc[2][8][4];
        #pragma unroll
        for(int m=0;m<2;m++)
            #pragma unroll
            for(int n=0;n<8;n++){ acc[m][n][0]=0.f;acc[m][n][1]=0.f;acc[m][n][2]=0.f;acc[m][n][3]=0.f; }

        for(int dc=0; dc<8; dc++){
            const int j = nt*8 + dc;
            const int s = j & 3;
            MBAR_WAIT(fullb+s*8, (j>>2)&1);
            const char* stp = smem + BOFF + (size_t)s*BSTG;
            const char* sta = smem + (size_t)dc*4096;

            #pragma unroll
            for(int ks=0; ks<2; ks++){
                uint4 af[2]; uint4 bq[4];
                #pragma unroll
                for(int m=0;m<2;m++)
                    af[m] = *(const uint4*)(sta + (((wm*2+m)*2+ks)*32+lane)*16);
                #pragma unroll
                for(int p=0;p<4;p++)
                    bq[p] = *(const uint4*)(stp + (((wn*4+p)*2+ks)*32+lane)*16);
                #pragma unroll
                for(int m=0;m<2;m++)
                    #pragma unroll
                    for(int p=0;p<4;p++){
                        mma16(acc[m][2*p],   (const uint32_t*)&af[m], &bq[p].x);
                        mma16(acc[m][2*p+1], (const uint32_t*)&af[m], &bq[p].z);
                    }
            }
            __syncwarp();
            if(lane==0) MBAR_ARRIVE(emptyb+s*8);
            // distributed producer: warp (j&7) lane0 prefetches iter j+NSTG-1
            if(wid == (j&7) && lane==0 && j+NSTG-1 < NIT){
                const int jj = j+NSTG-1;
                const int sj = jj & 3;
                if(jj >= NSTG) MBAR_WAIT(emptyb+sj*8, ((jj>>2)-1)&1);
                MBAR_EXPECT_TX(fullb+sj*8, BSTG);
                BULK_G2S(sb + BOFF + sj*BSTG,
                         (const char*)g_ep + (size_t)jj*BSTG, BSTG, fullb+sj*8);
            }
        }
        // branchless fold of this 256-col tile (cols ascending per slot)
        #pragma unroll
        for(int n=0;n<8;n++){
            int colb = nt*BN + wn*64 + n*8 + 2*c;
            float e0 = __ldg(esq+colb), e1 = __ldg(esq+colb+1);
            #pragma unroll
            for(int m=0;m<2;m++){
                const int rl=2*m, rh=2*m+1;
                float d;
                d = fmaf(-2.f, acc[m][n][0], e0);
                m2[rl] = fminf(fmaxf(d, m1[rl]), m2[rl]);
                i1[rl] = (d < m1[rl]) ? colb : i1[rl];
                m1[rl] = fminf(d, m1[rl]);
                d = fmaf(-2.f, acc[m][n][1], e1);
                m2[rl] = fminf(fmaxf(d, m1[rl]), m2[rl]);
                i1[rl] = (d < m1[rl]) ? colb+1 : i1[rl];
                m1[rl] = fminf(d, m1[rl]);
                d = fmaf(-2.f, acc[m][n][2], e0);
                m2[rh] = fminf(fmaxf(d, m1[rh]), m2[rh]);
                i1[rh] = (d < m1[rh]) ? colb : i1[rh];
                m1[rh] = fminf(d, m1[rh]);
                d = fmaf(-2.f, acc[m][n][3], e1);
                m2[rh] = fminf(fmaxf(d, m1[rh]), m2[rh]);
                i1[rh] = (d < m1[rh]) ? colb+1 : i1[rh];
                m1[rh] = fminf(d, m1[rh]);
            }
        }
    }

    // epilogue reduction overlays the (now dead) B stage buffers
    float* s_m1 = (float*)(smem + BOFF);            // 64*16*4 = 4KB
    float* s_m2 = (float*)(smem + BOFF + 4096);
    int*   s_i1 = (int*)(smem + BOFF + 8192);
    int*   s_idx= (int*)(smem + BOFF + 12288);
    __syncthreads();
    #pragma unroll
    for(int i=0;i<4;i++){
        int row  = wm*32 + (i>>1)*16 + r + (i&1)*8;
        int slot = wn*4 + c;
        s_m1[row*16+slot] = m1[i];
        s_m2[row*16+slot] = m2[i];
        s_i1[row*16+slot] = i1[i];
    }
    __syncthreads();
    if(tid < BM){
        float bd = 3.4e38f; int bi = 0, tw = 0;
        #pragma unroll
        for(int t=0;t<16;t++){
            float d = s_m1[tid*16+t]; int ii = s_i1[tid*16+t];
            if(d<bd || (d==bd && ii<bi)){ bd=d; bi=ii; tw=t; }
        }
        float b2 = 3.4e38f;
        #pragma unroll
        for(int t=0;t<16;t++){
            float v = (t==tw) ? s_m2[tid*16+t] : s_m1[tid*16+t];
            b2 = fminf(b2, v);
        }
        s_idx[tid] = bi;
        outi[m0+tid] = (float)bi;
        if(b2 - bd < FLAG_T){
            g_best[m0+tid] = 0xFFFFFFFFFFFFFFFFull;
            int pos = atomicAdd(&g_cnt, 1);
            if(pos < FLAG_CAP) g_flag[pos] = m0 + tid;
        }
    }
    __syncthreads();
    for(int f=tid; f<BM*(DD/4); f+=NTHR){
        int rr = f>>6, c4 = f&63;
        float4 v = *(const float4*)(E + (size_t)s_idx[rr]*DD + c4*4);
        *(float4*)(outq + (size_t)(m0+rr)*DD + c4*4) = v;
    }
}

// ---- phase 2: exact fp32 rescore, K-split, atomicMin merge ----
__global__ void __launch_bounds__(128) vq_phase2(
    const float* __restrict__ X, const float* __restrict__ E, const float* __restrict__ esq)
{
    int cnt = g_cnt; if(cnt > FLAG_CAP) cnt = FLAG_CAP;
    const int rb = blockIdx.x;
    if(rb*P2M >= cnt) return;
    const int k0 = blockIdx.y * 128;
    __shared__ float Xs[16][P2M];
    __shared__ float Es[16][128];
    __shared__ int rows[P2M];
    __shared__ float s_bd[16][P2M];
    __shared__ int   s_bi[16][P2M];
    const int tid = threadIdx.x;
    const int tx = tid&15, ty = tid>>4;
    if(tid < P2M){
        int fi = rb*P2M + tid; if(fi >= cnt) fi = cnt-1;
        rows[tid] = g_flag[fi];
    }
    __syncthreads();

    float acc[8][8];
    #pragma unroll
    for(int i=0;i<8;i++)
        #pragma unroll
        for(int j=0;j<8;j++) acc[i][j]=0.f;

    for(int d0=0; d0<DD; d0+=16){
        #pragma unroll
        for(int l=0;l<2;l++){
            int f = tid + l*128, rr = f>>2, c4 = f&3;
            float4 v = *(const float4*)(X + (size_t)rows[rr]*DD + d0 + c4*4);
            Xs[c4*4+0][rr]=v.x; Xs[c4*4+1][rr]=v.y; Xs[c4*4+2][rr]=v.z; Xs[c4*4+3][rr]=v.w;
        }
        #pragma unroll
        for(int l=0;l<4;l++){
            int f = tid + l*128, rr = f>>2, c4 = f&3;
            float4 v = *(const float4*)(E + (size_t)(k0+rr)*DD + d0 + c4*4);
            Es[c4*4+0][rr]=v.x; Es[c4*4+1][rr]=v.y; Es[c4*4+2][rr]=v.z; Es[c4*4+3][rr]=v.w;
        }
        __syncthreads();
        #pragma unroll
        for(int kk=0;kk<16;kk++){
            float xr[8], er[8];
            #pragma unroll
            for(int i=0;i<8;i++) xr[i]=Xs[kk][ty*8+i];
            #pragma unroll
            for(int j=0;j<8;j++) er[j]=Es[kk][tx*8+j];
            #pragma unroll
            for(int i=0;i<8;i++)
                #pragma unroll
                for(int j=0;j<8;j++) acc[i][j]=fmaf(xr[i],er[j],acc[i][j]);
        }
        __syncthreads();
    }
    float bd[8]; int bi[8];
    #pragma unroll
    for(int i=0;i<8;i++){ bd[i]=3.4e38f; bi[i]=0; }
    #pragma unroll
    for(int i=0;i<8;i++)
        #pragma unroll
        for(int j=0;j<8;j++){
            int col = k0 + tx*8 + j;
            float d = __ldg(esq+col) - 2.f*acc[i][j];
            if(d < bd[i]){ bd[i]=d; bi[i]=col; }
        }
    #pragma unroll
    for(int i=0;i<8;i++){ s_bd[tx][ty*8+i]=bd[i]; s_bi[tx][ty*8+i]=bi[i]; }
    __syncthreads();
    if(tid < P2M){
        float b = s_bd[0][tid]; int ii = s_bi[0][tid];
        #pragma unroll
        for(int t=1;t<16;t++){
            float d = s_bd[t][tid]; int jj = s_bi[t][tid];
            if(d<b || (d==b && jj<ii)){ b=d; ii=jj; }
        }
        if(rb*P2M + tid < cnt){
            uint32_t u = __float_as_uint(b);
            u = (u & 0x80000000u) ? ~u : (u | 0x80000000u);
            unsigned long long key = ((unsigned long long)u << 32) | (unsigned)ii;
            atomicMin(&g_best[rows[tid]], key);
        }
    }
}

// ---- phase 3: write back flagged rows ----
__global__ void __launch_bounds__(256) vq_phase3(
    const float* __restrict__ E, float* __restrict__ outq, float* __restrict__ outi)
{
    int cnt = g_cnt; if(cnt > FLAG_CAP) cnt = FLAG_CAP;
    int i = blockIdx.x*8 + (threadIdx.x>>5);
    if(i >= cnt) return;
    int lane = threadIdx.x&31;
    int row = g_flag[i];
    int bi = (int)(g_best[row] & 0xFFFFFFFFull);
    if(lane==0) outi[row] = (float)bi;
    float4 v0 = *(const float4*)(E + (size_t)bi*DD + lane*8);
    float4 v1 = *(const float4*)(E + (size_t)bi*DD + lane*8 + 4);
    *(float4*)(outq + (size_t)row*DD + lane*8)     = v0;
    *(float4*)(outq + (size_t)row*DD + lane*8 + 4) = v1;
}

extern "C" void kernel_launch(void* const* d_in, const int* in_sizes, int n_in,
                              void* d_out, int out_size) {
    const float* X = (const float*)d_in[0];
    const float* E = (const float*)d_in[1];

    uint4* xp; uint2* ep; float* esq;
    cudaGetSymbolAddress((void**)&xp, g_xp);
    cudaGetSymbolAddress((void**)&ep, g_ep);
    cudaGetSymbolAddress((void**)&esq, g_esq);

    packA<<<NTOK*DD*2/16/256, 256>>>(X, xp);
    packB<<<KCB*DD*2/8/256, 256>>>(E, ep);
    sumsq_kernel<<<KCB/8, 256>>>(E, esq, KCB);   // also zeroes g_cnt

    float* outq = (float*)d_out;
    float* outi = (float*)d_out + (size_t)NTOK*DD;

    cudaFuncSetAttribute(vq_phase1, cudaFuncAttributeMaxDynamicSharedMemorySize, SMEMSZ);
    vq_phase1<<<NMB, NTHR, SMEMSZ>>>(E, esq, outq, outi);
    vq_phase2<<<dim3(FLAG_CAP/P2M, KCB/128), 128>>>(X, E, esq);
    vq_phase3<<<FLAG_CAP/8, 256>>>(E, outq, outi);
}

// round 14
// speedup vs baseline: 1.9000x; 1.0478x over previous
#include <cuda_runtime.h>
#include <cuda_fp16.h>
#include <cstdint>

#define DD 256
#define NTOK 16384
#define KCB 8192
#define BM 64
#define BN 256
#define NMB (NTOK/BM)     // 256
#define NNT (KCB/BN)      // 32
#define NIT (NNT*8)       // 256
#define ASZ 32768
#define BSTG 16384
#define NSTG 4
#define BOFF ASZ
#define BARS (ASZ + NSTG*BSTG)   // 98304
#define SMEMSZ (BARS + 256)
#define NTHR 256
#define FLAG_T 0.12f
#define FLAG_CAP 4096
#define P2M 64

__device__ __align__(128) uint4 g_xp[NTOK*DD*2/16];
__device__ __align__(128) uint2 g_ep[KCB*DD*2/8];
__device__ __align__(128) float g_esq[KCB];
__device__ unsigned long long g_best[NTOK];
__device__ int g_flag[FLAG_CAP];
__device__ int g_cnt;

__device__ __forceinline__ uint32_t s2u(const void* p){
    uint32_t a; asm("{ .reg .u64 t; cvta.to.shared.u64 t, %1; cvt.u32.u64 %0, t; }":"=r"(a):"l"(p)); return a;
}
#define MBAR_INIT(a,c) asm volatile("mbarrier.init.shared.b64 [%0], %1;"::"r"(a),"r"(c):"memory")
#define MBAR_ARRIVE(a) asm volatile("mbarrier.arrive.shared.b64 _, [%0];"::"r"(a):"memory")
#define MBAR_EXPECT_TX(a,tx) asm volatile("mbarrier.arrive.expect_tx.shared.b64 _, [%0], %1;"::"r"(a),"r"(tx):"memory")
#define MBAR_WAIT(a,p) do{ uint32_t _m=(a),_p=(p),_d; \
    asm volatile("{\n\t.reg .pred q;\n\tmbarrier.try_wait.parity.acquire.cta.shared::cta.b64 q,[%1],%2;\n\tselp.b32 %0,1,0,q;\n\t}":"=r"(_d):"r"(_m),"r"(_p):"memory"); \
    if(!_d){ asm volatile("{\n\t.reg .pred q;\n\tW%=:\n\tmbarrier.try_wait.parity.acquire.cta.shared::cta.b64 q,[%0],%1,0x989680;\n\t@q bra.uni DN%=;\n\tbra.uni W%=;\n\tDN%=:\n\t}"::"r"(_m),"r"(_p):"memory"); } }while(0)
#define BULK_G2S(d,s,n,mb) asm volatile( \
    "cp.async.bulk.shared::cluster.global.mbarrier::complete_tx::bytes [%0], [%1], %2, [%3];" \
    :: "r"((uint32_t)(d)),"l"(s),"r"((uint32_t)(n)),"r"((uint32_t)(mb)) : "memory")

__device__ __forceinline__ void mma16(float* d, const uint32_t* a, const uint32_t* b){
    asm("mma.sync.aligned.m16n8k16.row.col.f32.f16.f16.f32 "
        "{%0,%1,%2,%3}, {%4,%5,%6,%7}, {%8,%9}, {%0,%1,%2,%3};"
        : "+f"(d[0]),"+f"(d[1]),"+f"(d[2]),"+f"(d[3])
        : "r"(a[0]),"r"(a[1]),"r"(a[2]),"r"(a[3]),"r"(b[0]),"r"(b[1]));
}

// ---- prep: pack A fp16 fragments ([mb 256][dc 8][tl 4][ks 2][lane 32]) ----
__global__ void packA(const float* __restrict__ src, uint4* __restrict__ dst){
    int i = blockIdx.x*blockDim.x + threadIdx.x;
    int lane = i&31, ks = (i>>5)&1, tl = (i>>6)&3, dc = (i>>8)&7, mb = i>>11;
    int gr = lane>>2, t = lane&3;
    int r0 = (mb*4+tl)*16 + gr;
    int k0 = dc*32 + ks*16 + 2*t;
    const float* p0 = src + (size_t)r0*DD;
    const float* p1 = src + (size_t)(r0+8)*DD;
    __half h[8];
    h[0]=__float2half_rn(p0[k0]);   h[1]=__float2half_rn(p0[k0+1]);
    h[2]=__float2half_rn(p1[k0]);   h[3]=__float2half_rn(p1[k0+1]);
    h[4]=__float2half_rn(p0[k0+8]); h[5]=__float2half_rn(p0[k0+9]);
    h[6]=__float2half_rn(p1[k0+8]); h[7]=__float2half_rn(p1[k0+9]);
    dst[i] = *(const uint4*)h;
}
// ---- prep: pack B fp16 fragments (n8-tiles paired for LDS.128) ----
__global__ void packB(const float* __restrict__ src, uint2* __restrict__ dst){
    int i = blockIdx.x*blockDim.x + threadIdx.x;
    int lane = i&31, ks = (i>>5)&1, ntl = (i>>6)&31, dc = (i>>11)&7, nt = i>>14;
    int gr = lane>>2, t = lane&3;
    int col = nt*BN + ntl*8 + gr;
    int k0 = dc*32 + ks*16 + 2*t;
    const float* p = src + (size_t)col*DD;
    __half h[4];
    h[0]=__float2half_rn(p[k0]);   h[1]=__float2half_rn(p[k0+1]);
    h[2]=__float2half_rn(p[k0+8]); h[3]=__float2half_rn(p[k0+9]);
    size_t blk = (size_t)(nt*8+dc)*16384;
    size_t off = blk + ((((size_t)(ntl>>1)*2+ks)*32+lane)<<4) + ((ntl&1)<<3);
    dst[off>>3] = *(const uint2*)h;
}
__global__ void sumsq_kernel(const float* __restrict__ x, float* __restrict__ o, int rows){
    if(blockIdx.x==0 && threadIdx.x==0) g_cnt = 0;
    int row = blockIdx.x*(blockDim.x>>5) + (threadIdx.x>>5); if(row>=rows) return;
    int lane = threadIdx.x&31; const float* p = x + (size_t)row*DD; float s=0.f;
    #pragma unroll
    for(int c=lane;c<DD;c+=32){ float v=p[c]; s+=v*v; }
    #pragma unroll
    for(int ofs=16;ofs;ofs>>=1) s+=__shfl_down_sync(0xffffffffu,s,ofs);
    if(!lane) o[row]=s;
}

// ---- phase 1: fp16 GEMM, ks-level software pipeline, 2 CTAs/SM ----
__global__ void __launch_bounds__(NTHR,2) vq_phase1(
    const float* __restrict__ E, const float* __restrict__ esq,
    float* __restrict__ outq, float* __restrict__ outi)
{
    extern __shared__ char smem[];
    const uint32_t sb = s2u(smem);
    const int tid = threadIdx.x, wid = tid>>5, lane = tid&31;
    const int r = lane>>2, c = lane&3;
    const int wm = wid&1, wn = wid>>1;     // 2x4 warp grid, warp tile 32x64
    const int mb = blockIdx.x, m0 = mb*BM;

    const uint32_t abar   = sb + BARS;
    const uint32_t fullb  = sb + BARS + 16;
    const uint32_t emptyb = sb + BARS + 64;

    if(tid==0){
        MBAR_INIT(abar,1);
        #pragma unroll
        for(int s=0;s<NSTG;s++){ MBAR_INIT(fullb+s*8,1); MBAR_INIT(emptyb+s*8,8); }
    }
    __syncthreads();
    if(tid==0){
        MBAR_EXPECT_TX(abar, ASZ);
        BULK_G2S(sb, (const char*)g_xp + (size_t)mb*ASZ, ASZ, abar);
        #pragma unroll
        for(int j=0;j<NSTG-1;j++){
            MBAR_EXPECT_TX(fullb+j*8, BSTG);
            BULK_G2S(sb + BOFF + j*BSTG, (const char*)g_ep + (size_t)j*BSTG, BSTG, fullb+j*8);
        }
    }
    MBAR_WAIT(abar, 0);

    float m1[4], m2[4]; int i1[4];
    #pragma unroll
    for(int i=0;i<4;i++){ m1[i]=3.4e38f; m2[i]=3.4e38f; i1[i]=0; }

    for(int nt=0; nt<NNT; nt++){
        float acc[2][8][4];
        #pragma unroll
        for(int m=0;m<2;m++)
            #pragma unroll
            for(int n=0;n<8;n++){ acc[m][n][0]=0.f;acc[m][n][1]=0.f;acc[m][n][2]=0.f;acc[m][n][3]=0.f; }

        const int j0 = nt*8;
        uint4 bq[2][4];
        // prologue: wait dc0 stage, preload step0 B frags
        MBAR_WAIT(fullb + (j0&3)*8, (j0>>2)&1);
        {
            const char* stp = smem + BOFF + (size_t)(j0&3)*BSTG;
            #pragma unroll
            for(int p=0;p<4;p++)
                bq[0][p] = *(const uint4*)(stp + ((wn*4+p)*2*32+lane)*16);
        }

        #pragma unroll
        for(int step=0; step<16; step++){
            const int dc = step>>1, ks = step&1, cb = step&1;
            const int j = j0 + dc, s = j&3;
            // prefetch next step's B fragments into the other buffer
            if(step < 15){
                const int ns = step+1, ndc = ns>>1, nks = ns&1;
                const int jn = j0 + ndc, sn = jn&3;
                if(nks==0) MBAR_WAIT(fullb + sn*8, (jn>>2)&1);
                const char* stpn = smem + BOFF + (size_t)sn*BSTG;
                #pragma unroll
                for(int p=0;p<4;p++)
                    bq[ns&1][p] = *(const uint4*)(stpn + (((wn*4+p)*2+nks)*32+lane)*16);
            }
            // A fragments just-in-time
            const char* sta = smem + (size_t)dc*4096;
            uint4 af0 = *(const uint4*)(sta + ((wm*4+ks)*32+lane)*16);
            uint4 af1 = *(const uint4*)(sta + (((wm*2+1)*2+ks)*32+lane)*16);
            #pragma unroll
            for(int p=0;p<4;p++){
                mma16(acc[0][2*p],   &af0.x, &bq[cb][p].x);
                mma16(acc[0][2*p+1], &af0.x, &bq[cb][p].z);
                mma16(acc[1][2*p],   &af1.x, &bq[cb][p].x);
                mma16(acc[1][2*p+1], &af1.x, &bq[cb][p].z);
            }
            if(ks==1){
                __syncwarp();
                if(lane==0) MBAR_ARRIVE(emptyb + s*8);
                if(wid == (j&7) && lane==0 && j+NSTG-1 < NIT){
                    const int jj = j+NSTG-1, sj = jj&3;
                    if(jj >= NSTG) MBAR_WAIT(emptyb + sj*8, ((jj>>2)-1)&1);
                    MBAR_EXPECT_TX(fullb + sj*8, BSTG);
                    BULK_G2S(sb + BOFF + sj*BSTG,
                             (const char*)g_ep + (size_t)jj*BSTG, BSTG, fullb + sj*8);
                }
            }
        }
        // branchless fold of this 256-col tile (cols ascending per slot)
        #pragma unroll
        for(int n=0;n<8;n++){
            int colb = nt*BN + wn*64 + n*8 + 2*c;
            float e0 = __ldg(esq+colb), e1 = __ldg(esq+colb+1);
            #pragma unroll
            for(int m=0;m<2;m++){
                const int rl=2*m, rh=2*m+1;
                float d;
                d = fmaf(-2.f, acc[m][n][0], e0);
                m2[rl] = fminf(fmaxf(d, m1[rl]), m2[rl]);
                i1[rl] = (d < m1[rl]) ? colb : i1[rl];
                m1[rl] = fminf(d, m1[rl]);
                d = fmaf(-2.f, acc[m][n][1], e1);
                m2[rl] = fminf(fmaxf(d, m1[rl]), m2[rl]);
                i1[rl] = (d < m1[rl]) ? colb+1 : i1[rl];
                m1[rl] = fminf(d, m1[rl]);
                d = fmaf(-2.f, acc[m][n][2], e0);
                m2[rh] = fminf(fmaxf(d, m1[rh]), m2[rh]);
                i1[rh] = (d < m1[rh]) ? colb : i1[rh];
                m1[rh] = fminf(d, m1[rh]);
                d = fmaf(-2.f, acc[m][n][3], e1);
                m2[rh] = fminf(fmaxf(d, m1[rh]), m2[rh]);
                i1[rh] = (d < m1[rh]) ? colb+1 : i1[rh];
                m1[rh] = fminf(d, m1[rh]);
            }
        }
    }

    // epilogue reduction overlays the (now dead) B stage buffers
    float* s_m1 = (float*)(smem + BOFF);
    float* s_m2 = (float*)(smem + BOFF + 4096);
    int*   s_i1 = (int*)(smem + BOFF + 8192);
    int*   s_idx= (int*)(smem + BOFF + 12288);
    __syncthreads();
    #pragma unroll
    for(int i=0;i<4;i++){
        int row  = wm*32 + (i>>1)*16 + r + (i&1)*8;
        int slot = wn*4 + c;
        s_m1[row*16+slot] = m1[i];
        s_m2[row*16+slot] = m2[i];
        s_i1[row*16+slot] = i1[i];
    }
    __syncthreads();
    if(tid < BM){
        float bd = 3.4e38f; int bi = 0, tw = 0;
        #pragma unroll
        for(int t=0;t<16;t++){
            float d = s_m1[tid*16+t]; int ii = s_i1[tid*16+t];
            if(d<bd || (d==bd && ii<bi)){ bd=d; bi=ii; tw=t; }
        }
        float b2 = 3.4e38f;
        #pragma unroll
        for(int t=0;t<16;t++){
            float v = (t==tw) ? s_m2[tid*16+t] : s_m1[tid*16+t];
            b2 = fminf(b2, v);
        }
        s_idx[tid] = bi;
        outi[m0+tid] = (float)bi;
        if(b2 - bd < FLAG_T){
            g_best[m0+tid] = 0xFFFFFFFFFFFFFFFFull;
            int pos = atomicAdd(&g_cnt, 1);
            if(pos < FLAG_CAP) g_flag[pos] = m0 + tid;
        }
    }
    __syncthreads();
    for(int f=tid; f<BM*(DD/4); f+=NTHR){
        int rr = f>>6, c4 = f&63;
        float4 v = *(const float4*)(E + (size_t)s_idx[rr]*DD + c4*4);
        *(float4*)(outq + (size_t)(m0+rr)*DD + c4*4) = v;
    }
}

// ---- phase 2: exact fp32 rescore, K-split, atomicMin merge ----
__global__ void __launch_bounds__(128) vq_phase2(
    const float* __restrict__ X, const float* __restrict__ E, const float* __restrict__ esq)
{
    int cnt = g_cnt; if(cnt > FLAG_CAP) cnt = FLAG_CAP;
    const int rb = blockIdx.x;
    if(rb*P2M >= cnt) return;
    const int k0 = blockIdx.y * 128;
    __shared__ float Xs[16][P2M];
    __shared__ float Es[16][128];
    __shared__ int rows[P2M];
    __shared__ float s_bd[16][P2M];
    __shared__ int   s_bi[16][P2M];
    const int tid = threadIdx.x;
    const int tx = tid&15, ty = tid>>4;
    if(tid < P2M){
        int fi = rb*P2M + tid; if(fi >= cnt) fi = cnt-1;
        rows[tid] = g_flag[fi];
    }
    __syncthreads();

    float acc[8][8];
    #pragma unroll
    for(int i=0;i<8;i++)
        #pragma unroll
        for(int j=0;j<8;j++) acc[i][j]=0.f;

    for(int d0=0; d0<DD; d0+=16){
        #pragma unroll
        for(int l=0;l<2;l++){
            int f = tid + l*128, rr = f>>2, c4 = f&3;
            float4 v = *(const float4*)(X + (size_t)rows[rr]*DD + d0 + c4*4);
            Xs[c4*4+0][rr]=v.x; Xs[c4*4+1][rr]=v.y; Xs[c4*4+2][rr]=v.z; Xs[c4*4+3][rr]=v.w;
        }
        #pragma unroll
        for(int l=0;l<4;l++){
            int f = tid + l*128, rr = f>>2, c4 = f&3;
            float4 v = *(const float4*)(E + (size_t)(k0+rr)*DD + d0 + c4*4);
            Es[c4*4+0][rr]=v.x; Es[c4*4+1][rr]=v.y; Es[c4*4+2][rr]=v.z; Es[c4*4+3][rr]=v.w;
        }
        __syncthreads();
        #pragma unroll
        for(int kk=0;kk<16;kk++){
            float xr[8], er[8];
            #pragma unroll
            for(int i=0;i<8;i++) xr[i]=Xs[kk][ty*8+i];
            #pragma unroll
            for(int j=0;j<8;j++) er[j]=Es[kk][tx*8+j];
            #pragma unroll
            for(int i=0;i<8;i++)
                #pragma unroll
                for(int j=0;j<8;j++) acc[i][j]=fmaf(xr[i],er[j],acc[i][j]);
        }
        __syncthreads();
    }
    float bd[8]; int bi[8];
    #pragma unroll
    for(int i=0;i<8;i++){ bd[i]=3.4e38f; bi[i]=0; }
    #pragma unroll
    for(int i=0;i<8;i++)
        #pragma unroll
        for(int j=0;j<8;j++){
            int col = k0 + tx*8 + j;
            float d = __ldg(esq+col) - 2.f*acc[i][j];
            if(d < bd[i]){ bd[i]=d; bi[i]=col; }
        }
    #pragma unroll
    for(int i=0;i<8;i++){ s_bd[tx][ty*8+i]=bd[i]; s_bi[tx][ty*8+i]=bi[i]; }
    __syncthreads();
    if(tid < P2M){
        float b = s_bd[0][tid]; int ii = s_bi[0][tid];
        #pragma unroll
        for(int t=1;t<16;t++){
            float d = s_bd[t][tid]; int jj = s_bi[t][tid];
            if(d<b || (d==b && jj<ii)){ b=d; ii=jj; }
        }
        if(rb*P2M + tid < cnt){
            uint32_t u = __float_as_uint(b);
            u = (u & 0x80000000u) ? ~u : (u | 0x80000000u);
            unsigned long long key = ((unsigned long long)u << 32) | (unsigned)ii;
            atomicMin(&g_best[rows[tid]], key);
        }
    }
}

// ---- phase 3: write back flagged rows ----
__global__ void __launch_bounds__(256) vq_phase3(
    const float* __restrict__ E, float* __restrict__ outq, float* __restrict__ outi)
{
    int cnt = g_cnt; if(cnt > FLAG_CAP) cnt = FLAG_CAP;
    int i = blockIdx.x*8 + (threadIdx.x>>5);
    if(i >= cnt) return;
    int lane = threadIdx.x&31;
    int row = g_flag[i];
    int bi = (int)(g_best[row] & 0xFFFFFFFFull);
    if(lane==0) outi[row] = (float)bi;
    float4 v0 = *(const float4*)(E + (size_t)bi*DD + lane*8);
    float4 v1 = *(const float4*)(E + (size_t)bi*DD + lane*8 + 4);
    *(float4*)(outq + (size_t)row*DD + lane*8)     = v0;
    *(float4*)(outq + (size_t)row*DD + lane*8 + 4) = v1;
}

extern "C" void kernel_launch(void* const* d_in, const int* in_sizes, int n_in,
                              void* d_out, int out_size) {
    const float* X = (const float*)d_in[0];
    const float* E = (const float*)d_in[1];

    uint4* xp; uint2* ep; float* esq;
    cudaGetSymbolAddress((void**)&xp, g_xp);
    cudaGetSymbolAddress((void**)&ep, g_ep);
    cudaGetSymbolAddress((void**)&esq, g_esq);

    packA<<<NTOK*DD*2/16/256, 256>>>(X, xp);
    packB<<<KCB*DD*2/8/256, 256>>>(E, ep);
    sumsq_kernel<<<KCB/8, 256>>>(E, esq, KCB);   // also zeroes g_cnt

    float* outq = (float*)d_out;
    float* outi = (float*)d_out + (size_t)NTOK*DD;

    cudaFuncSetAttribute(vq_phase1, cudaFuncAttributeMaxDynamicSharedMemorySize, SMEMSZ);
    vq_phase1<<<NMB, NTHR, SMEMSZ>>>(E, esq, outq, outi);
    vq_phase2<<<dim3(FLAG_CAP/P2M, KCB/128), 128>>>(X, E, esq);
    vq_phase3<<<FLAG_CAP/8, 256>>>(E, outq, outi);
}

// round 15
// speedup vs baseline: 1.9150x; 1.0079x over previous
#include <cuda_runtime.h>
#include <cuda_fp16.h>
#include <cstdint>

#define DD 256
#define NTOK 16384
#define KCB 8192
#define BM 64
#define BN 256
#define NMB (NTOK/BM)     // 256
#define NNT (KCB/BN)      // 32
#define NITG 128          // 32KB B chunks total
#define ASZ 32768
#define BSTG 32768
#define NSTG 2
#define BOFF ASZ
#define BARS (ASZ + NSTG*BSTG)   // 98304
#define SMEMSZ (BARS + 256)
#define NTHR 256
#define FLAG_T 0.12f
#define FLAG_CAP 4096
#define P2M 128

__device__ __align__(128) uint4 g_xp[NTOK*DD*2/16];
__device__ __align__(128) uint2 g_ep[KCB*DD*2/8];
__device__ __align__(128) float g_esq[KCB];
__device__ unsigned long long g_best[NTOK];
__device__ int g_flag[FLAG_CAP];
__device__ int g_cnt;

__device__ __forceinline__ uint32_t s2u(const void* p){
    uint32_t a; asm("{ .reg .u64 t; cvta.to.shared.u64 t, %1; cvt.u32.u64 %0, t; }":"=r"(a):"l"(p)); return a;
}
#define MBAR_INIT(a,c) asm volatile("mbarrier.init.shared.b64 [%0], %1;"::"r"(a),"r"(c):"memory")
#define MBAR_ARRIVE(a) asm volatile("mbarrier.arrive.shared.b64 _, [%0];"::"r"(a):"memory")
#define MBAR_EXPECT_TX(a,tx) asm volatile("mbarrier.arrive.expect_tx.shared.b64 _, [%0], %1;"::"r"(a),"r"(tx):"memory")
#define MBAR_WAIT(a,p) do{ uint32_t _m=(a),_p=(p),_d; \
    asm volatile("{\n\t.reg .pred q;\n\tmbarrier.try_wait.parity.acquire.cta.shared::cta.b64 q,[%1],%2;\n\tselp.b32 %0,1,0,q;\n\t}":"=r"(_d):"r"(_m),"r"(_p):"memory"); \
    if(!_d){ asm volatile("{\n\t.reg .pred q;\n\tW%=:\n\tmbarrier.try_wait.parity.acquire.cta.shared::cta.b64 q,[%0],%1,0x989680;\n\t@q bra.uni DN%=;\n\tbra.uni W%=;\n\tDN%=:\n\t}"::"r"(_m),"r"(_p):"memory"); } }while(0)
#define BULK_G2S(d,s,n,mb) asm volatile( \
    "cp.async.bulk.shared::cluster.global.mbarrier::complete_tx::bytes [%0], [%1], %2, [%3];" \
    :: "r"((uint32_t)(d)),"l"(s),"r"((uint32_t)(n)),"r"((uint32_t)(mb)) : "memory")

__device__ __forceinline__ void mma16(float* d, const uint32_t* a, const uint32_t* b){
    asm("mma.sync.aligned.m16n8k16.row.col.f32.f16.f16.f32 "
        "{%0,%1,%2,%3}, {%4,%5,%6,%7}, {%8,%9}, {%0,%1,%2,%3};"
        : "+f"(d[0]),"+f"(d[1]),"+f"(d[2]),"+f"(d[3])
        : "r"(a[0]),"r"(a[1]),"r"(a[2]),"r"(a[3]),"r"(b[0]),"r"(b[1]));
}

// ---- prep: pack A fp16 fragments ([mb 256][dc 8][tl 4][ks 2][lane 32]) ----
__global__ void packA(const float* __restrict__ src, uint4* __restrict__ dst){
    int i = blockIdx.x*blockDim.x + threadIdx.x;
    int lane = i&31, ks = (i>>5)&1, tl = (i>>6)&3, dc = (i>>8)&7, mb = i>>11;
    int gr = lane>>2, t = lane&3;
    int r0 = (mb*4+tl)*16 + gr;
    int k0 = dc*32 + ks*16 + 2*t;
    const float* p0 = src + (size_t)r0*DD;
    const float* p1 = src + (size_t)(r0+8)*DD;
    __half h[8];
    h[0]=__float2half_rn(p0[k0]);   h[1]=__float2half_rn(p0[k0+1]);
    h[2]=__float2half_rn(p1[k0]);   h[3]=__float2half_rn(p1[k0+1]);
    h[4]=__float2half_rn(p0[k0+8]); h[5]=__float2half_rn(p0[k0+9]);
    h[6]=__float2half_rn(p1[k0+8]); h[7]=__float2half_rn(p1[k0+9]);
    dst[i] = *(const uint4*)h;
}
// ---- prep: pack B fp16 fragments (n8-tiles paired for LDS.128) ----
__global__ void packB(const float* __restrict__ src, uint2* __restrict__ dst){
    int i = blockIdx.x*blockDim.x + threadIdx.x;
    int lane = i&31, ks = (i>>5)&1, ntl = (i>>6)&31, dc = (i>>11)&7, nt = i>>14;
    int gr = lane>>2, t = lane&3;
    int col = nt*BN + ntl*8 + gr;
    int k0 = dc*32 + ks*16 + 2*t;
    const float* p = src + (size_t)col*DD;
    __half h[4];
    h[0]=__float2half_rn(p[k0]);   h[1]=__float2half_rn(p[k0+1]);
    h[2]=__float2half_rn(p[k0+8]); h[3]=__float2half_rn(p[k0+9]);
    size_t blk = (size_t)(nt*8+dc)*16384;
    size_t off = blk + ((((size_t)(ntl>>1)*2+ks)*32+lane)<<4) + ((ntl&1)<<3);
    dst[off>>3] = *(const uint2*)h;
}
__global__ void sumsq_kernel(const float* __restrict__ x, float* __restrict__ o, int rows){
    if(blockIdx.x==0 && threadIdx.x==0) g_cnt = 0;
    int row = blockIdx.x*(blockDim.x>>5) + (threadIdx.x>>5); if(row>=rows) return;
    int lane = threadIdx.x&31; const float* p = x + (size_t)row*DD; float s=0.f;
    #pragma unroll
    for(int c=lane;c<DD;c+=32){ float v=p[c]; s+=v*v; }
    #pragma unroll
    for(int ofs=16;ofs;ofs>>=1) s+=__shfl_down_sync(0xffffffffu,s,ofs);
    if(!lane) o[row]=s;
}

// ---- phase 1: fp16 GEMM, 32KB B stages (NSTG=2), ks pipeline, 2 CTAs/SM ----
__global__ void __launch_bounds__(NTHR,2) vq_phase1(
    const float* __restrict__ E, const float* __restrict__ esq,
    float* __restrict__ outq, float* __restrict__ outi)
{
    extern __shared__ char smem[];
    const uint32_t sb = s2u(smem);
    const int tid = threadIdx.x, wid = tid>>5, lane = tid&31;
    const int r = lane>>2, c = lane&3;
    const int wm = wid&1, wn = wid>>1;     // 2x4 warp grid, warp tile 32x64
    const int mb = blockIdx.x, m0 = mb*BM;

    const uint32_t abar   = sb + BARS;
    const uint32_t fullb  = sb + BARS + 16;
    const uint32_t emptyb = sb + BARS + 48;

    if(tid==0){
        MBAR_INIT(abar,1);
        #pragma unroll
        for(int s=0;s<NSTG;s++){ MBAR_INIT(fullb+s*8,1); MBAR_INIT(emptyb+s*8,8); }
    }
    __syncthreads();
    if(tid==0){
        MBAR_EXPECT_TX(abar, ASZ);
        BULK_G2S(sb, (const char*)g_xp + (size_t)mb*ASZ, ASZ, abar);
        #pragma unroll
        for(int j=0;j<NSTG;j++){
            MBAR_EXPECT_TX(fullb+j*8, BSTG);
            BULK_G2S(sb + BOFF + j*BSTG, (const char*)g_ep + (size_t)j*BSTG, BSTG, fullb+j*8);
        }
    }
    MBAR_WAIT(abar, 0);

    float m1[4], m2[4]; int i1[4];
    #pragma unroll
    for(int i=0;i<4;i++){ m1[i]=3.4e38f; m2[i]=3.4e38f; i1[i]=0; }

    for(int nt=0; nt<NNT; nt++){
        float acc[2][8][4];
        #pragma unroll
        for(int m=0;m<2;m++)
            #pragma unroll
            for(int n=0;n<8;n++){ acc[m][n][0]=0.f;acc[m][n][1]=0.f;acc[m][n][2]=0.f;acc[m][n][3]=0.f; }

        const int g0 = nt*4;                  // first 32KB chunk of this nt
        uint4 bq[2][4];
        MBAR_WAIT(fullb + (g0&1)*8, (g0>>1)&1);
        {
            const char* stp = smem + BOFF + (size_t)(g0&1)*BSTG;   // half=0, ks=0
            #pragma unroll
            for(int p=0;p<4;p++)
                bq[0][p] = *(const uint4*)(stp + ((wn*4+p)*2*32+lane)*16);
        }

        #pragma unroll
        for(int step=0; step<16; step++){
            const int ks = step&1, cb = step&1;
            const int g = g0 + (step>>2);
            // prefetch next step's B fragments into the other buffer
            if(step < 15){
                const int ns = step+1;
                const int ng = g0 + (ns>>2), nhalf = (ns>>1)&1, nks = ns&1;
                if((ns&3)==0) MBAR_WAIT(fullb + (ng&1)*8, (ng>>1)&1);
                const char* stpn = smem + BOFF + (size_t)(ng&1)*BSTG + nhalf*16384;
                #pragma unroll
                for(int p=0;p<4;p++)
                    bq[ns&1][p] = *(const uint4*)(stpn + (((wn*4+p)*2+nks)*32+lane)*16);
            }
            // A fragments just-in-time (A addressed by absolute dc = step>>1)
            const char* sta = smem + (size_t)(step>>1)*4096;
            uint4 af0 = *(const uint4*)(sta + ((wm*4+ks)*32+lane)*16);
            uint4 af1 = *(const uint4*)(sta + (((wm*2+1)*2+ks)*32+lane)*16);
            #pragma unroll
            for(int p=0;p<4;p++){
                mma16(acc[0][2*p],   &af0.x, &bq[cb][p].x);
                mma16(acc[0][2*p+1], &af0.x, &bq[cb][p].z);
                mma16(acc[1][2*p],   &af1.x, &bq[cb][p].x);
                mma16(acc[1][2*p+1], &af1.x, &bq[cb][p].z);
            }
            if((step&3)==3){
                __syncwarp();
                if(lane==0) MBAR_ARRIVE(emptyb + (g&1)*8);
                if(wid == (g&7) && lane==0 && g+2 < NITG){
                    const int jj = g+2, sj = jj&1;
                    MBAR_WAIT(emptyb + sj*8, ((jj>>1)-1)&1);
                    MBAR_EXPECT_TX(fullb + sj*8, BSTG);
                    BULK_G2S(sb + BOFF + sj*BSTG,
                             (const char*)g_ep + (size_t)jj*BSTG, BSTG, fullb + sj*8);
                }
            }
        }
        // branchless fold of this 256-col tile (cols ascending per slot)
        #pragma unroll
        for(int n=0;n<8;n++){
            int colb = nt*BN + wn*64 + n*8 + 2*c;
            float e0 = __ldg(esq+colb), e1 = __ldg(esq+colb+1);
            #pragma unroll
            for(int m=0;m<2;m++){
                const int rl=2*m, rh=2*m+1;
                float d;
                d = fmaf(-2.f, acc[m][n][0], e0);
                m2[rl] = fminf(fmaxf(d, m1[rl]), m2[rl]);
                i1[rl] = (d < m1[rl]) ? colb : i1[rl];
                m1[rl] = fminf(d, m1[rl]);
                d = fmaf(-2.f, acc[m][n][1], e1);
                m2[rl] = fminf(fmaxf(d, m1[rl]), m2[rl]);
                i1[rl] = (d < m1[rl]) ? colb+1 : i1[rl];
                m1[rl] = fminf(d, m1[rl]);
                d = fmaf(-2.f, acc[m][n][2], e0);
                m2[rh] = fminf(fmaxf(d, m1[rh]), m2[rh]);
                i1[rh] = (d < m1[rh]) ? colb : i1[rh];
                m1[rh] = fminf(d, m1[rh]);
                d = fmaf(-2.f, acc[m][n][3], e1);
                m2[rh] = fminf(fmaxf(d, m1[rh]), m2[rh]);
                i1[rh] = (d < m1[rh]) ? colb+1 : i1[rh];
                m1[rh] = fminf(d, m1[rh]);
            }
        }
    }

    // epilogue reduction overlays the (now dead) B stage buffers
    float* s_m1 = (float*)(smem + BOFF);
    float* s_m2 = (float*)(smem + BOFF + 4096);
    int*   s_i1 = (int*)(smem + BOFF + 8192);
    int*   s_idx= (int*)(smem + BOFF + 12288);
    __syncthreads();
    #pragma unroll
    for(int i=0;i<4;i++){
        int row  = wm*32 + (i>>1)*16 + r + (i&1)*8;
        int slot = wn*4 + c;
        s_m1[row*16+slot] = m1[i];
        s_m2[row*16+slot] = m2[i];
        s_i1[row*16+slot] = i1[i];
    }
    __syncthreads();
    if(tid < BM){
        float bd = 3.4e38f; int bi = 0, tw = 0;
        #pragma unroll
        for(int t=0;t<16;t++){
            float d = s_m1[tid*16+t]; int ii = s_i1[tid*16+t];
            if(d<bd || (d==bd && ii<bi)){ bd=d; bi=ii; tw=t; }
        }
        float b2 = 3.4e38f;
        #pragma unroll
        for(int t=0;t<16;t++){
            float v = (t==tw) ? s_m2[tid*16+t] : s_m1[tid*16+t];
            b2 = fminf(b2, v);
        }
        s_idx[tid] = bi;
        outi[m0+tid] = (float)bi;
        if(b2 - bd < FLAG_T){
            g_best[m0+tid] = 0xFFFFFFFFFFFFFFFFull;
            int pos = atomicAdd(&g_cnt, 1);
            if(pos < FLAG_CAP) g_flag[pos] = m0 + tid;
        }
    }
    __syncthreads();
    for(int f=tid; f<BM*(DD/4); f+=NTHR){
        int rr = f>>6, c4 = f&63;
        float4 v = *(const float4*)(E + (size_t)s_idx[rr]*DD + c4*4);
        *(float4*)(outq + (size_t)(m0+rr)*DD + c4*4) = v;
    }
}

// ---- phase 2: exact fp32 rescore, 128x128 tiles, atomicMin merge ----
__global__ void __launch_bounds__(256) vq_phase2(
    const float* __restrict__ X, const float* __restrict__ E, const float* __restrict__ esq)
{
    int cnt = g_cnt; if(cnt > FLAG_CAP) cnt = FLAG_CAP;
    const int rb = blockIdx.x;
    if(rb*P2M >= cnt) return;
    const int k0 = blockIdx.y * 128;
    __shared__ float Xs[16][P2M];
    __shared__ float Es[16][128];
    __shared__ int rows[P2M];
    __shared__ float s_bd[16][P2M];
    __shared__ int   s_bi[16][P2M];
    const int tid = threadIdx.x;
    const int tx = tid&15, ty = tid>>4;
    if(tid < P2M){
        int fi = rb*P2M + tid; if(fi >= cnt) fi = cnt-1;
        rows[tid] = g_flag[fi];
    }
    __syncthreads();

    float acc[8][8];
    #pragma unroll
    for(int i=0;i<8;i++)
        #pragma unroll
        for(int j=0;j<8;j++) acc[i][j]=0.f;

    for(int d0=0; d0<DD; d0+=16){
        #pragma unroll
        for(int l=0;l<2;l++){
            int f = tid + l*256, rr = f>>2, c4 = f&3;
            float4 v = *(const float4*)(X + (size_t)rows[rr]*DD + d0 + c4*4);
            Xs[c4*4+0][rr]=v.x; Xs[c4*4+1][rr]=v.y; Xs[c4*4+2][rr]=v.z; Xs[c4*4+3][rr]=v.w;
        }
        #pragma unroll
        for(int l=0;l<2;l++){
            int f = tid + l*256, rr = f>>2, c4 = f&3;
            float4 v = *(const float4*)(E + (size_t)(k0+rr)*DD + d0 + c4*4);
            Es[c4*4+0][rr]=v.x; Es[c4*4+1][rr]=v.y; Es[c4*4+2][rr]=v.z; Es[c4*4+3][rr]=v.w;
        }
        __syncthreads();
        #pragma unroll
        for(int kk=0;kk<16;kk++){
            float xr[8], er[8];
            #pragma unroll
            for(int i=0;i<8;i++) xr[i]=Xs[kk][ty*8+i];
            #pragma unroll
            for(int j=0;j<8;j++) er[j]=Es[kk][tx*8+j];
            #pragma unroll
            for(int i=0;i<8;i++)
                #pragma unroll
                for(int j=0;j<8;j++) acc[i][j]=fmaf(xr[i],er[j],acc[i][j]);
        }
        __syncthreads();
    }
    float bd[8]; int bi[8];
    #pragma unroll
    for(int i=0;i<8;i++){ bd[i]=3.4e38f; bi[i]=0; }
    #pragma unroll
    for(int i=0;i<8;i++)
        #pragma unroll
        for(int j=0;j<8;j++){
            int col = k0 + tx*8 + j;
            float d = __ldg(esq+col) - 2.f*acc[i][j];
            if(d < bd[i]){ bd[i]=d; bi[i]=col; }
        }
    #pragma unroll
    for(int i=0;i<8;i++){ s_bd[tx][ty*8+i]=bd[i]; s_bi[tx][ty*8+i]=bi[i]; }
    __syncthreads();
    if(tid < P2M){
        float b = s_bd[0][tid]; int ii = s_bi[0][tid];
        #pragma unroll
        for(int t=1;t<16;t++){
            float d = s_bd[t][tid]; int jj = s_bi[t][tid];
            if(d<b || (d==b && jj<ii)){ b=d; ii=jj; }
        }
        if(rb*P2M + tid < cnt){
            uint32_t u = __float_as_uint(b);
            u = (u & 0x80000000u) ? ~u : (u | 0x80000000u);
            unsigned long long key = ((unsigned long long)u << 32) | (unsigned)ii;
            atomicMin(&g_best[rows[tid]], key);
        }
    }
}

// ---- phase 3: write back flagged rows ----
__global__ void __launch_bounds__(256) vq_phase3(
    const float* __restrict__ E, float* __restrict__ outq, float* __restrict__ outi)
{
    int cnt = g_cnt; if(cnt > FLAG_CAP) cnt = FLAG_CAP;
    int i = blockIdx.x*8 + (threadIdx.x>>5);
    if(i >= cnt) return;
    int lane = threadIdx.x&31;
    int row = g_flag[i];
    int bi = (int)(g_best[row] & 0xFFFFFFFFull);
    if(lane==0) outi[row] = (float)bi;
    float4 v0 = *(const float4*)(E + (size_t)bi*DD + lane*8);
    float4 v1 = *(const float4*)(E + (size_t)bi*DD + lane*8 + 4);
    *(float4*)(outq + (size_t)row*DD + lane*8)     = v0;
    *(float4*)(outq + (size_t)row*DD + lane*8 + 4) = v1;
}

extern "C" void kernel_launch(void* const* d_in, const int* in_sizes, int n_in,
                              void* d_out, int out_size) {
    const float* X = (const float*)d_in[0];
    const float* E = (const float*)d_in[1];

    uint4* xp; uint2* ep; float* esq;
    cudaGetSymbolAddress((void**)&xp, g_xp);
    cudaGetSymbolAddress((void**)&ep, g_ep);
    cudaGetSymbolAddress((void**)&esq, g_esq);

    packA<<<NTOK*DD*2/16/256, 256>>>(X, xp);
    packB<<<KCB*DD*2/8/256, 256>>>(E, ep);
    sumsq_kernel<<<KCB/8, 256>>>(E, esq, KCB);   // also zeroes g_cnt

    float* outq = (float*)d_out;
    float* outi = (float*)d_out + (size_t)NTOK*DD;

    cudaFuncSetAttribute(vq_phase1, cudaFuncAttributeMaxDynamicSharedMemorySize, SMEMSZ);
    vq_phase1<<<NMB, NTHR, SMEMSZ>>>(E, esq, outq, outi);
    vq_phase2<<<dim3(FLAG_CAP/P2M, KCB/128), 256>>>(X, E, esq);
    vq_phase3<<<FLAG_CAP/8, 256>>>(E, outq, outi);
}

// round 16
// speedup vs baseline: 2.0044x; 1.0467x over previous
#include <cuda_runtime.h>
#include <cuda_fp16.h>
#include <cstdint>

#define DD 256
#define NTOK 16384
#define KCB 8192
#define BM 128
#define BN 256
#define NMB (NTOK/BM)     // 128
#define NNT (KCB/BN)      // 32
#define NITG 128          // 32KB B chunks
#define ASZ 65536         // A panel: 8 dc x 8KB (fp16, 128 rows)
#define BSTG 32768
#define NSTG 4
#define BOFF ASZ
#define BARS (ASZ + NSTG*BSTG)   // 196608
#define SMEMSZ (BARS + 256)
#define NTHR 256
#define FLAG_T 0.12f
#define FLAG_CAP 4096
#define P2M 128

__device__ __align__(128) uint4 g_xp[NTOK*DD*2/16];
__device__ __align__(128) uint2 g_ep[KCB*DD*2/8];
__device__ __align__(128) float g_esq[KCB];
__device__ unsigned long long g_best[NTOK];
__device__ int g_flag[FLAG_CAP];
__device__ int g_cnt;

__device__ __forceinline__ uint32_t s2u(const void* p){
    uint32_t a; asm("{ .reg .u64 t; cvta.to.shared.u64 t, %1; cvt.u32.u64 %0, t; }":"=r"(a):"l"(p)); return a;
}
#define MBAR_INIT(a,c) asm volatile("mbarrier.init.shared.b64 [%0], %1;"::"r"(a),"r"(c):"memory")
#define MBAR_ARRIVE(a) asm volatile("mbarrier.arrive.shared.b64 _, [%0];"::"r"(a):"memory")
#define MBAR_EXPECT_TX(a,tx) asm volatile("mbarrier.arrive.expect_tx.shared.b64 _, [%0], %1;"::"r"(a),"r"(tx):"memory")
#define MBAR_WAIT(a,p) do{ uint32_t _m=(a),_p=(p),_d; \
    asm volatile("{\n\t.reg .pred q;\n\tmbarrier.try_wait.parity.acquire.cta.shared::cta.b64 q,[%1],%2;\n\tselp.b32 %0,1,0,q;\n\t}":"=r"(_d):"r"(_m),"r"(_p):"memory"); \
    if(!_d){ asm volatile("{\n\t.reg .pred q;\n\tW%=:\n\tmbarrier.try_wait.parity.acquire.cta.shared::cta.b64 q,[%0],%1,0x989680;\n\t@q bra.uni DN%=;\n\tbra.uni W%=;\n\tDN%=:\n\t}"::"r"(_m),"r"(_p):"memory"); } }while(0)
#define BULK_G2S(d,s,n,mb) asm volatile( \
    "cp.async.bulk.shared::cluster.global.mbarrier::complete_tx::bytes [%0], [%1], %2, [%3];" \
    :: "r"((uint32_t)(d)),"l"(s),"r"((uint32_t)(n)),"r"((uint32_t)(mb)) : "memory")

__device__ __forceinline__ void mma16(float* d, const uint32_t* a, const uint32_t* b){
    asm("mma.sync.aligned.m16n8k16.row.col.f32.f16.f16.f32 "
        "{%0,%1,%2,%3}, {%4,%5,%6,%7}, {%8,%9}, {%0,%1,%2,%3};"
        : "+f"(d[0]),"+f"(d[1]),"+f"(d[2]),"+f"(d[3])
        : "r"(a[0]),"r"(a[1]),"r"(a[2]),"r"(a[3]),"r"(b[0]),"r"(b[1]));
}

// ---- prep: pack A fp16 fragments ([mb 128][dc 8][tl 8][ks 2][lane 32]) ----
__global__ void packA(const float* __restrict__ src, uint4* __restrict__ dst){
    int i = blockIdx.x*blockDim.x + threadIdx.x;
    int lane = i&31, ks = (i>>5)&1, tl = (i>>6)&7, dc = (i>>9)&7, mb = i>>12;
    int gr = lane>>2, t = lane&3;
    int r0 = mb*BM + tl*16 + gr;
    int k0 = dc*32 + ks*16 + 2*t;
    const float* p0 = src + (size_t)r0*DD;
    const float* p1 = src + (size_t)(r0+8)*DD;
    __half h[8];
    h[0]=__float2half_rn(p0[k0]);   h[1]=__float2half_rn(p0[k0+1]);
    h[2]=__float2half_rn(p1[k0]);   h[3]=__float2half_rn(p1[k0+1]);
    h[4]=__float2half_rn(p0[k0+8]); h[5]=__float2half_rn(p0[k0+9]);
    h[6]=__float2half_rn(p1[k0+8]); h[7]=__float2half_rn(p1[k0+9]);
    dst[i] = *(const uint4*)h;
}
// ---- prep: pack B fp16 fragments (n8-tiles paired for LDS.128) ----
__global__ void packB(const float* __restrict__ src, uint2* __restrict__ dst){
    int i = blockIdx.x*blockDim.x + threadIdx.x;
    int lane = i&31, ks = (i>>5)&1, ntl = (i>>6)&31, dc = (i>>11)&7, nt = i>>14;
    int gr = lane>>2, t = lane&3;
    int col = nt*BN + ntl*8 + gr;
    int k0 = dc*32 + ks*16 + 2*t;
    const float* p = src + (size_t)col*DD;
    __half h[4];
    h[0]=__float2half_rn(p[k0]);   h[1]=__float2half_rn(p[k0+1]);
    h[2]=__float2half_rn(p[k0+8]); h[3]=__float2half_rn(p[k0+9]);
    size_t blk = (size_t)(nt*8+dc)*16384;
    size_t off = blk + ((((size_t)(ntl>>1)*2+ks)*32+lane)<<4) + ((ntl&1)<<3);
    dst[off>>3] = *(const uint2*)h;
}
__global__ void sumsq_kernel(const float* __restrict__ x, float* __restrict__ o, int rows){
    if(blockIdx.x==0 && threadIdx.x==0) g_cnt = 0;
    int row = blockIdx.x*(blockDim.x>>5) + (threadIdx.x>>5); if(row>=rows) return;
    int lane = threadIdx.x&31; const float* p = x + (size_t)row*DD; float s=0.f;
    #pragma unroll
    for(int c=lane;c<DD;c+=32){ float v=p[c]; s+=v*v; }
    #pragma unroll
    for(int ofs=16;ofs;ofs>>=1) s+=__shfl_down_sync(0xffffffffu,s,ofs);
    if(!lane) o[row]=s;
}

// ---- phase 1: BM=128, warp tile 64x64, 1 CTA/SM, fp16 GEMM ----
__global__ void __launch_bounds__(NTHR,1) vq_phase1(
    const float* __restrict__ E, const float* __restrict__ esq,
    float* __restrict__ outq, float* __restrict__ outi)
{
    extern __shared__ char smem[];
    const uint32_t sb = s2u(smem);
    const int tid = threadIdx.x, wid = tid>>5, lane = tid&31;
    const int r = lane>>2, c = lane&3;
    const int wm = wid&1, wn = wid>>1;     // 2x4 warp grid, warp tile 64x64
    const int mb = blockIdx.x, m0 = mb*BM;

    const uint32_t abar   = sb + BARS;
    const uint32_t fullb  = sb + BARS + 16;
    const uint32_t emptyb = sb + BARS + 64;

    if(tid==0){
        MBAR_INIT(abar,1);
        #pragma unroll
        for(int s=0;s<NSTG;s++){ MBAR_INIT(fullb+s*8,1); MBAR_INIT(emptyb+s*8,8); }
    }
    __syncthreads();
    if(tid==0){
        MBAR_EXPECT_TX(abar, ASZ);
        BULK_G2S(sb, (const char*)g_xp + (size_t)mb*ASZ, ASZ, abar);
        #pragma unroll
        for(int j=0;j<NSTG-1;j++){
            MBAR_EXPECT_TX(fullb+j*8, BSTG);
            BULK_G2S(sb + BOFF + j*BSTG, (const char*)g_ep + (size_t)j*BSTG, BSTG, fullb+j*8);
        }
    }
    MBAR_WAIT(abar, 0);

    float m1[8], m2[8]; int i1[8];
    #pragma unroll
    for(int i=0;i<8;i++){ m1[i]=3.4e38f; m2[i]=3.4e38f; i1[i]=0; }

    for(int nt=0; nt<NNT; nt++){
        float acc[4][8][4];
        #pragma unroll
        for(int m=0;m<4;m++)
            #pragma unroll
            for(int n=0;n<8;n++){ acc[m][n][0]=0.f;acc[m][n][1]=0.f;acc[m][n][2]=0.f;acc[m][n][3]=0.f; }

        const int g0 = nt*4;
        uint4 bq[2][4];
        MBAR_WAIT(fullb + (g0&3)*8, (g0>>2)&1);
        {
            const char* stp = smem + BOFF + (size_t)(g0&3)*BSTG;
            #pragma unroll
            for(int p=0;p<4;p++)
                bq[0][p] = *(const uint4*)(stp + ((wn*4+p)*2*32+lane)*16);
        }

        #pragma unroll
        for(int step=0; step<16; step++){
            const int ks = step&1, cb = step&1;
            const int g = g0 + (step>>2);
            // prefetch next step's B fragments into the other buffer
            if(step < 15){
                const int ns = step+1;
                const int ng = g0 + (ns>>2), nhalf = (ns>>1)&1, nks = ns&1;
                if((ns&3)==0) MBAR_WAIT(fullb + (ng&3)*8, (ng>>2)&1);
                const char* stpn = smem + BOFF + (size_t)(ng&3)*BSTG + nhalf*16384;
                #pragma unroll
                for(int p=0;p<4;p++)
                    bq[ns&1][p] = *(const uint4*)(stpn + (((wn*4+p)*2+nks)*32+lane)*16);
            }
            // A fragments just-in-time (4 m16 tiles per warp)
            const char* sta = smem + (size_t)(step>>1)*8192;
            #pragma unroll
            for(int mi=0; mi<4; mi++){
                uint4 af = *(const uint4*)(sta + (((wm*4+mi)*2+ks)*32+lane)*16);
                #pragma unroll
                for(int p=0;p<4;p++){
                    mma16(acc[mi][2*p],   &af.x, &bq[cb][p].x);
                    mma16(acc[mi][2*p+1], &af.x, &bq[cb][p].z);
                }
            }
            if((step&3)==3){
                __syncwarp();
                if(lane==0) MBAR_ARRIVE(emptyb + (g&3)*8);
                if(wid == (g&7) && lane==0 && g+3 < NITG){
                    const int jj = g+3, sj = jj&3;
                    if(jj >= NSTG) MBAR_WAIT(emptyb + sj*8, ((jj>>2)-1)&1);
                    MBAR_EXPECT_TX(fullb + sj*8, BSTG);
                    BULK_G2S(sb + BOFF + sj*BSTG,
                             (const char*)g_ep + (size_t)jj*BSTG, BSTG, fullb + sj*8);
                }
            }
        }
        // branchless fold of this 256-col tile (cols ascending per slot)
        #pragma unroll
        for(int n=0;n<8;n++){
            int colb = nt*BN + wn*64 + n*8 + 2*c;
            float e0 = __ldg(esq+colb), e1 = __ldg(esq+colb+1);
            #pragma unroll
            for(int mi=0;mi<4;mi++){
                const int rl=2*mi, rh=2*mi+1;
                float d;
                d = fmaf(-2.f, acc[mi][n][0], e0);
                m2[rl] = fminf(fmaxf(d, m1[rl]), m2[rl]);
                i1[rl] = (d < m1[rl]) ? colb : i1[rl];
                m1[rl] = fminf(d, m1[rl]);
                d = fmaf(-2.f, acc[mi][n][1], e1);
                m2[rl] = fminf(fmaxf(d, m1[rl]), m2[rl]);
                i1[rl] = (d < m1[rl]) ? colb+1 : i1[rl];
                m1[rl] = fminf(d, m1[rl]);
                d = fmaf(-2.f, acc[mi][n][2], e0);
                m2[rh] = fminf(fmaxf(d, m1[rh]), m2[rh]);
                i1[rh] = (d < m1[rh]) ? colb : i1[rh];
                m1[rh] = fminf(d, m1[rh]);
                d = fmaf(-2.f, acc[mi][n][3], e1);
                m2[rh] = fminf(fmaxf(d, m1[rh]), m2[rh]);
                i1[rh] = (d < m1[rh]) ? colb+1 : i1[rh];
                m1[rh] = fminf(d, m1[rh]);
            }
        }
    }

    // epilogue reduction overlays the (now dead) B stage buffers
    float* s_m1 = (float*)(smem + BOFF);            // 128*16*4 = 8KB each
    float* s_m2 = (float*)(smem + BOFF + 8192);
    int*   s_i1 = (int*)(smem + BOFF + 16384);
    int*   s_idx= (int*)(smem + BOFF + 24576);
    __syncthreads();
    #pragma unroll
    for(int i=0;i<8;i++){
        int row  = wm*64 + (i>>1)*16 + r + (i&1)*8;
        int slot = wn*4 + c;
        s_m1[row*16+slot] = m1[i];
        s_m2[row*16+slot] = m2[i];
        s_i1[row*16+slot] = i1[i];
    }
    __syncthreads();
    if(tid < BM){
        float bd = 3.4e38f; int bi = 0, tw = 0;
        #pragma unroll
        for(int t=0;t<16;t++){
            float d = s_m1[tid*16+t]; int ii = s_i1[tid*16+t];
            if(d<bd || (d==bd && ii<bi)){ bd=d; bi=ii; tw=t; }
        }
        float b2 = 3.4e38f;
        #pragma unroll
        for(int t=0;t<16;t++){
            float v = (t==tw) ? s_m2[tid*16+t] : s_m1[tid*16+t];
            b2 = fminf(b2, v);
        }
        s_idx[tid] = bi;
        outi[m0+tid] = (float)bi;
        if(b2 - bd < FLAG_T){
            g_best[m0+tid] = 0xFFFFFFFFFFFFFFFFull;
            int pos = atomicAdd(&g_cnt, 1);
            if(pos < FLAG_CAP) g_flag[pos] = m0 + tid;
        }
    }
    __syncthreads();
    for(int f=tid; f<BM*(DD/4); f+=NTHR){
        int rr = f>>6, c4 = f&63;
        float4 v = *(const float4*)(E + (size_t)s_idx[rr]*DD + c4*4);
        *(float4*)(outq + (size_t)(m0+rr)*DD + c4*4) = v;
    }
}

// ---- phase 2: exact fp32 rescore, 128x128 tiles, atomicMin merge ----
__global__ void __launch_bounds__(256) vq_phase2(
    const float* __restrict__ X, const float* __restrict__ E, const float* __restrict__ esq)
{
    int cnt = g_cnt; if(cnt > FLAG_CAP) cnt = FLAG_CAP;
    const int rb = blockIdx.x;
    if(rb*P2M >= cnt) return;
    const int k0 = blockIdx.y * 128;
    __shared__ float Xs[16][P2M];
    __shared__ float Es[16][128];
    __shared__ int rows[P2M];
    __shared__ float s_bd[16][P2M];
    __shared__ int   s_bi[16][P2M];
    const int tid = threadIdx.x;
    const int tx = tid&15, ty = tid>>4;
    if(tid < P2M){
        int fi = rb*P2M + tid; if(fi >= cnt) fi = cnt-1;
        rows[tid] = g_flag[fi];
    }
    __syncthreads();

    float acc[8][8];
    #pragma unroll
    for(int i=0;i<8;i++)
        #pragma unroll
        for(int j=0;j<8;j++) acc[i][j]=0.f;

    for(int d0=0; d0<DD; d0+=16){
        #pragma unroll
        for(int l=0;l<2;l++){
            int f = tid + l*256, rr = f>>2, c4 = f&3;
            float4 v = *(const float4*)(X + (size_t)rows[rr]*DD + d0 + c4*4);
            Xs[c4*4+0][rr]=v.x; Xs[c4*4+1][rr]=v.y; Xs[c4*4+2][rr]=v.z; Xs[c4*4+3][rr]=v.w;
        }
        #pragma unroll
        for(int l=0;l<2;l++){
            int f = tid + l*256, rr = f>>2, c4 = f&3;
            float4 v = *(const float4*)(E + (size_t)(k0+rr)*DD + d0 + c4*4);
            Es[c4*4+0][rr]=v.x; Es[c4*4+1][rr]=v.y; Es[c4*4+2][rr]=v.z; Es[c4*4+3][rr]=v.w;
        }
        __syncthreads();
        #pragma unroll
        for(int kk=0;kk<16;kk++){
            float xr[8], er[8];
            #pragma unroll
            for(int i=0;i<8;i++) xr[i]=Xs[kk][ty*8+i];
            #pragma unroll
            for(int j=0;j<8;j++) er[j]=Es[kk][tx*8+j];
            #pragma unroll
            for(int i=0;i<8;i++)
                #pragma unroll
                for(int j=0;j<8;j++) acc[i][j]=fmaf(xr[i],er[j],acc[i][j]);
        }
        __syncthreads();
    }
    float bd[8]; int bi[8];
    #pragma unroll
    for(int i=0;i<8;i++){ bd[i]=3.4e38f; bi[i]=0; }
    #pragma unroll
    for(int i=0;i<8;i++)
        #pragma unroll
        for(int j=0;j<8;j++){
            int col = k0 + tx*8 + j;
            float d = __ldg(esq+col) - 2.f*acc[i][j];
            if(d < bd[i]){ bd[i]=d; bi[i]=col; }
        }
    #pragma unroll
    for(int i=0;i<8;i++){ s_bd[tx][ty*8+i]=bd[i]; s_bi[tx][ty*8+i]=bi[i]; }
    __syncthreads();
    if(tid < P2M){
        float b = s_bd[0][tid]; int ii = s_bi[0][tid];
        #pragma unroll
        for(int t=1;t<16;t++){
            float d = s_bd[t][tid]; int jj = s_bi[t][tid];
            if(d<b || (d==b && jj<ii)){ b=d; ii=jj; }
        }
        if(rb*P2M + tid < cnt){
            uint32_t u = __float_as_uint(b);
            u = (u & 0x80000000u) ? ~u : (u | 0x80000000u);
            unsigned long long key = ((unsigned long long)u << 32) | (unsigned)ii;
            atomicMin(&g_best[rows[tid]], key);
        }
    }
}

// ---- phase 3: write back flagged rows ----
__global__ void __launch_bounds__(256) vq_phase3(
    const float* __restrict__ E, float* __restrict__ outq, float* __restrict__ outi)
{
    int cnt = g_cnt; if(cnt > FLAG_CAP) cnt = FLAG_CAP;
    int i = blockIdx.x*8 + (threadIdx.x>>5);
    if(i >= cnt) return;
    int lane = threadIdx.x&31;
    int row = g_flag[i];
    int bi = (int)(g_best[row] & 0xFFFFFFFFull);
    if(lane==0) outi[row] = (float)bi;
    float4 v0 = *(const float4*)(E + (size_t)bi*DD + lane*8);
    float4 v1 = *(const float4*)(E + (size_t)bi*DD + lane*8 + 4);
    *(float4*)(outq + (size_t)row*DD + lane*8)     = v0;
    *(float4*)(outq + (size_t)row*DD + lane*8 + 4) = v1;
}

extern "C" void kernel_launch(void* const* d_in, const int* in_sizes, int n_in,
                              void* d_out, int out_size) {
    const float* X = (const float*)d_in[0];
    const float* E = (const float*)d_in[1];

    uint4* xp; uint2* ep; float* esq;
    cudaGetSymbolAddress((void**)&xp, g_xp);
    cudaGetSymbolAddress((void**)&ep, g_ep);
    cudaGetSymbolAddress((void**)&esq, g_esq);

    packA<<<NTOK*DD*2/16/256, 256>>>(X, xp);
    packB<<<KCB*DD*2/8/256, 256>>>(E, ep);
    sumsq_kernel<<<KCB/8, 256>>>(E, esq, KCB);   // also zeroes g_cnt

    float* outq = (float*)d_out;
    float* outi = (float*)d_out + (size_t)NTOK*DD;

    cudaFuncSetAttribute(vq_phase1, cudaFuncAttributeMaxDynamicSharedMemorySize, SMEMSZ);
    vq_phase1<<<NMB, NTHR, SMEMSZ>>>(E, esq, outq, outi);
    vq_phase2<<<dim3(FLAG_CAP/P2M, KCB/128), 256>>>(X, E, esq);
    vq_phase3<<<FLAG_CAP/8, 256>>>(E, outq, outi);
}